// round 13
// baseline (speedup 1.0000x reference)
#include <cuda_runtime.h>
#include <cuda_bf16.h>
#include <cstdint>

#define S 3072
#define DIM 1536
#define H 12
#define NB 24
#define SCALE 0.08838834764831845f   // 1/sqrt(128)
#define NEG_BIG (-1e30f)
#define CHUNK 4
#define MAXCH 6                       // ceil(24/4)
#define NPAIR (H * NB)                // 288
#define NSLOT (NPAIR * MAXCH)         // 1728

// ---------------- scratch (device globals; no allocation allowed) ----------
__device__ float g_q[S * DIM];
__device__ float g_k[S * DIM];
__device__ float g_v[S * DIM];
__device__ float g_qw[NB * DIM];
__device__ float g_kw[NB * DIM];
__device__ float g_battn[H * NB * NB];
__device__ float g_thr[H];
__device__ int   g_list[H * NB * NB];
__device__ int   g_cnt[NPAIR];
__device__ int   g_items[NSLOT];
__device__ int   g_nch[NPAIR];
__device__ int   g_nwork;
// attention partials (split-KV): unnormalized O, row-max, row-den
__device__ float g_po[NSLOT * 128 * 128];
__device__ float g_pm[NSLOT * 128];
__device__ float g_pd[NSLOT * 128];

// bf16 hi/lo splits
__device__ __nv_bfloat16 s_xh[S * DIM],  s_xl[S * DIM];
__device__ __nv_bfloat16 s_ah[S * DIM],  s_al[S * DIM];
__device__ __nv_bfloat16 s_wqh[DIM * DIM], s_wql[DIM * DIM];
__device__ __nv_bfloat16 s_wkh[DIM * DIM], s_wkl[DIM * DIM];
__device__ __nv_bfloat16 s_wvh[DIM * DIM], s_wvl[DIM * DIM];
__device__ __nv_bfloat16 s_woh[DIM * DIM], s_wol[DIM * DIM];
__device__ __nv_bfloat16 s_qh[S * DIM], s_ql[S * DIM];
__device__ __nv_bfloat16 s_kh[S * DIM], s_kl[S * DIM];
__device__ __nv_bfloat16 s_vth[DIM * S], s_vtl[DIM * S];   // transposed [d][t]

// ---------------------------------------------------------------------------
__device__ __forceinline__ uint32_t smem_u32(const void* p) {
    uint32_t a;
    asm("{ .reg .u64 t; cvta.to.shared.u64 t, %1; cvt.u32.u64 %0, t; }"
        : "=r"(a) : "l"(p));
    return a;
}
__device__ __forceinline__ void cp16(uint32_t dst, const void* src) {
    asm volatile("cp.async.cg.shared.global [%0], [%1], 16;" :: "r"(dst), "l"(src));
}
#define CP_COMMIT() asm volatile("cp.async.commit_group;" ::: "memory")
#define CP_WAIT(n)  asm volatile("cp.async.wait_group %0;" :: "n"(n) : "memory")

__device__ __forceinline__ void mma_bf16(float* c, uint32_t a0, uint32_t a1,
                                         uint32_t a2, uint32_t a3,
                                         uint32_t b0, uint32_t b1) {
    asm volatile(
        "mma.sync.aligned.m16n8k16.row.col.f32.bf16.bf16.f32 "
        "{%0,%1,%2,%3}, {%4,%5,%6,%7}, {%8,%9}, {%0,%1,%2,%3};"
        : "+f"(c[0]), "+f"(c[1]), "+f"(c[2]), "+f"(c[3])
        : "r"(a0), "r"(a1), "r"(a2), "r"(a3), "r"(b0), "r"(b1));
}
__device__ __forceinline__ uint32_t pack2(float x, float y) {
    __nv_bfloat162 t = __floats2bfloat162_rn(x, y);
    return *(uint32_t*)&t;
}

// ---------------------------------------------------------------------------
__global__ __launch_bounds__(256) void split_kernel(
    const float* __restrict__ X, __nv_bfloat16* __restrict__ Hh,
    __nv_bfloat16* __restrict__ Hl)
{
    int i = blockIdx.x * 256 + threadIdx.x;
    float v = X[i];
    __nv_bfloat16 h = __float2bfloat16(v);
    Hh[i] = h;
    Hl[i] = __float2bfloat16(v - __bfloat162float(h));
}

// ---------------------------------------------------------------------------
__global__ __launch_bounds__(256) void vt_split(
    const float* __restrict__ V, __nv_bfloat16* __restrict__ Th,
    __nv_bfloat16* __restrict__ Tl)
{
    __shared__ float tile[32][33];
    const int t0 = blockIdx.x * 32, d0 = blockIdx.y * 32;
    const int tx = threadIdx.x & 31, ty = threadIdx.x >> 5;
#pragma unroll
    for (int i = 0; i < 4; i++)
        tile[ty + 8 * i][tx] = V[(size_t)(t0 + ty + 8 * i) * DIM + d0 + tx];
    __syncthreads();
#pragma unroll
    for (int i = 0; i < 4; i++) {
        float v = tile[tx][ty + 8 * i];
        __nv_bfloat16 h = __float2bfloat16(v);
        size_t o = (size_t)(d0 + ty + 8 * i) * S + t0 + tx;
        Th[o] = h;
        Tl[o] = __float2bfloat16(v - __bfloat162float(h));
    }
}

// ---------------------------------------------------------------------------
// mma.sync GEMM, bf16-split 3-product (proven). 3-stage cp.async pipeline.
// ---------------------------------------------------------------------------
#define TILEB 18432
#define STAGEB (4 * TILEB)
#define GEMM_SMEM (3 * STAGEB)

__global__ __launch_bounds__(256, 1) void gemm_mma(
    const __nv_bfloat16* __restrict__ Ah, const __nv_bfloat16* __restrict__ Al,
    const __nv_bfloat16* __restrict__ Wh0, const __nv_bfloat16* __restrict__ Wl0,
    const __nv_bfloat16* __restrict__ Wh1, const __nv_bfloat16* __restrict__ Wl1,
    const __nv_bfloat16* __restrict__ Wh2, const __nv_bfloat16* __restrict__ Wl2,
    const float* __restrict__ b0, const float* __restrict__ b1,
    const float* __restrict__ b2,
    float* __restrict__ C0, float* __restrict__ C1, float* __restrict__ C2)
{
    extern __shared__ char smem[];
    const int z = blockIdx.z;
    const __nv_bfloat16* Wh = z == 0 ? Wh0 : (z == 1 ? Wh1 : Wh2);
    const __nv_bfloat16* Wl = z == 0 ? Wl0 : (z == 1 ? Wl1 : Wl2);
    const float* bias = z == 0 ? b0 : (z == 1 ? b1 : b2);
    float* C = z == 0 ? C0 : (z == 1 ? C1 : C2);

    const int n0 = blockIdx.x * 128;
    const int m0 = blockIdx.y * 128;
    const int tid = threadIdx.x;
    const int lane = tid & 31, wid = tid >> 5;
    const int warp_m = wid & 3, warp_n = wid >> 2;
    const int g = lane >> 2, th = lane & 3;

    const uint32_t sbase = smem_u32(smem);

    auto load_stage = [&](int stage, int c) {
        const __nv_bfloat16* srcs[4] = {
            Ah + (size_t)m0 * DIM + c * 64,
            Al + (size_t)m0 * DIM + c * 64,
            Wh + (size_t)n0 * DIM + c * 64,
            Wl + (size_t)n0 * DIM + c * 64 };
        uint32_t stb = sbase + stage * STAGEB;
#pragma unroll
        for (int t = 0; t < 4; t++) {
#pragma unroll
            for (int u = 0; u < 4; u++) {
                int f = tid + 256 * u;
                int row = f >> 3, seg = f & 7;
                cp16(stb + t * TILEB + row * 144 + seg * 16,
                     srcs[t] + (size_t)row * DIM + seg * 8);
            }
        }
    };

    float acc[2][8][4];
#pragma unroll
    for (int i = 0; i < 2; i++)
#pragma unroll
        for (int j = 0; j < 8; j++)
#pragma unroll
            for (int r = 0; r < 4; r++) acc[i][j][r] = 0.f;

    load_stage(0, 0); CP_COMMIT();
    load_stage(1, 1); CP_COMMIT();

    for (int c = 0; c < 24; c++) {
        if (c < 23) { CP_WAIT(1); } else { CP_WAIT(0); }
        __syncthreads();

        const uint32_t* AhU = (const uint32_t*)(smem + ((c % 3) * STAGEB));
        const uint32_t* AlU = AhU + TILEB / 4;
        const uint32_t* WhU = AhU + 2 * (TILEB / 4);
        const uint32_t* WlU = AhU + 3 * (TILEB / 4);

#pragma unroll
        for (int ks = 0; ks < 4; ks++) {
            uint32_t ah[2][4], al[2][4];
#pragma unroll
            for (int mt = 0; mt < 2; mt++) {
                int mrow = warp_m * 32 + mt * 16 + g;
                int bidx = mrow * 36 + ks * 8 + th;
                ah[mt][0] = AhU[bidx];
                ah[mt][1] = AhU[bidx + 8 * 36];
                ah[mt][2] = AhU[bidx + 4];
                ah[mt][3] = AhU[bidx + 8 * 36 + 4];
                al[mt][0] = AlU[bidx];
                al[mt][1] = AlU[bidx + 8 * 36];
                al[mt][2] = AlU[bidx + 4];
                al[mt][3] = AlU[bidx + 8 * 36 + 4];
            }
#pragma unroll
            for (int j = 0; j < 8; j++) {
                int nrow = warp_n * 64 + j * 8 + g;
                int bidx = nrow * 36 + ks * 8 + th;
                uint32_t bh0 = WhU[bidx], bh1 = WhU[bidx + 4];
                uint32_t bl0 = WlU[bidx], bl1 = WlU[bidx + 4];
#pragma unroll
                for (int mt = 0; mt < 2; mt++) {
                    mma_bf16(acc[mt][j], ah[mt][0], ah[mt][1], ah[mt][2], ah[mt][3], bh0, bh1);
                    mma_bf16(acc[mt][j], ah[mt][0], ah[mt][1], ah[mt][2], ah[mt][3], bl0, bl1);
                    mma_bf16(acc[mt][j], al[mt][0], al[mt][1], al[mt][2], al[mt][3], bh0, bh1);
                }
            }
        }
        if (c + 2 < 24) { load_stage((c + 2) % 3, c + 2); CP_COMMIT(); }
        __syncthreads();
    }

#pragma unroll
    for (int mt = 0; mt < 2; mt++) {
        int r = m0 + warp_m * 32 + mt * 16 + g;
#pragma unroll
        for (int j = 0; j < 8; j++) {
            int col = n0 + warp_n * 64 + j * 8 + th * 2;
            float bx = bias[col], by = bias[col + 1];
            float2 o0 = { acc[mt][j][0] + bx, acc[mt][j][1] + by };
            float2 o1 = { acc[mt][j][2] + bx, acc[mt][j][3] + by };
            *(float2*)(C + (size_t)r * DIM + col) = o0;
            *(float2*)(C + (size_t)(r + 8) * DIM + col) = o1;
        }
    }
}

// ---------------------------------------------------------------------------
// RMSNorm + RoPE, fused bf16 hi/lo split output
// ---------------------------------------------------------------------------
__global__ __launch_bounds__(256) void norm_rope_kernel(
    float* __restrict__ Xq, float* __restrict__ Xk,
    __nv_bfloat16* __restrict__ Qh, __nv_bfloat16* __restrict__ Ql,
    __nv_bfloat16* __restrict__ Kh, __nv_bfloat16* __restrict__ Kl,
    const float* __restrict__ gq, const float* __restrict__ gk,
    const float* __restrict__ fc, const float* __restrict__ fs)
{
    const int s = blockIdx.x;
    float* X = blockIdx.y ? Xk : Xq;
    __nv_bfloat16* Oh = blockIdx.y ? Kh : Qh;
    __nv_bfloat16* Ol = blockIdx.y ? Kl : Ql;
    const float* g = blockIdx.y ? gk : gq;
    float* row = X + (size_t)s * 1536;
    const int tid = threadIdx.x;

    float ss = 0.f;
#pragma unroll
    for (int c = 0; c < 6; c++) {
        float v = row[tid + 256 * c];
        ss += v * v;
    }
#pragma unroll
    for (int o = 16; o >= 1; o >>= 1)
        ss += __shfl_xor_sync(0xffffffffu, ss, o);
    __shared__ float red[8];
    if ((tid & 31) == 0) red[tid >> 5] = ss;
    __syncthreads();
    float tot = 0.f;
#pragma unroll
    for (int w = 0; w < 8; w++) tot += red[w];
    float scale = rsqrtf(tot * (1.f / 1536.f) + 1e-5f);

#pragma unroll
    for (int u = 0; u < 3; u++) {
        int p = tid + 256 * u;
        int i = p & 63;
        float c = fc[s * 64 + i];
        float sn = fs[s * 64 + i];
        float x0 = row[2 * p] * scale * g[2 * p];
        float x1 = row[2 * p + 1] * scale * g[2 * p + 1];
        float y0 = x0 * c - x1 * sn;
        float y1 = x0 * sn + x1 * c;
        row[2 * p]     = y0;
        row[2 * p + 1] = y1;
        size_t o = (size_t)s * 1536 + 2 * p;
        __nv_bfloat16 h0 = __float2bfloat16(y0);
        __nv_bfloat16 h1 = __float2bfloat16(y1);
        Oh[o] = h0;     Oh[o + 1] = h1;
        Ol[o] = __float2bfloat16(y0 - __bfloat162float(h0));
        Ol[o + 1] = __float2bfloat16(y1 - __bfloat162float(h1));
    }
}

// ---------------------------------------------------------------------------
__global__ __launch_bounds__(256) void pool_mean(
    const float* __restrict__ Q, const float* __restrict__ Kx,
    float* __restrict__ qw, float* __restrict__ kw)
{
    const int nb = blockIdx.x;
    const float* X = blockIdx.y ? Kx : Q;
    float* Wo = blockIdx.y ? kw : qw;
    const int tid = threadIdx.x;
    float acc[6] = {0, 0, 0, 0, 0, 0};
    for (int t = 0; t < 128; t++) {
        const float* row = X + (size_t)(nb * 128 + t) * 1536;
#pragma unroll
        for (int c = 0; c < 6; c++) acc[c] += row[tid + 256 * c];
    }
#pragma unroll
    for (int c = 0; c < 6; c++)
        Wo[nb * 1536 + tid + 256 * c] = acc[c] * (1.f / 128.f);
}

// ---------------------------------------------------------------------------
__global__ void draft_scores(const float* __restrict__ qw,
                             const float* __restrict__ kw,
                             float* __restrict__ battn)
{
    const int h = blockIdx.x, l = blockIdx.y;
    const int m = threadIdx.x;
    float sc = NEG_BIG;
    if (m < 24) {
        int rl = l >> 2, cl = l & 3, rm = m >> 2, cm = m & 3;
        bool ok = (rm >= rl - 3) && (rm <= rl + 2) && (cm >= cl - 3) && (cm <= cl + 2);
        if (ok) {
            float sum = 0.f;
            const float* qr = qw + l * 1536 + h * 128;
            const float* kr = kw + m * 1536 + h * 128;
#pragma unroll 8
            for (int d = 0; d < 128; d++) sum += qr[d] * kr[d];
            sc = sum * SCALE;
        }
    }
    float mx = sc;
#pragma unroll
    for (int o = 16; o >= 1; o >>= 1)
        mx = fmaxf(mx, __shfl_xor_sync(0xffffffffu, mx, o));
    float e = __expf(sc - mx);
    float se = e;
#pragma unroll
    for (int o = 16; o >= 1; o >>= 1)
        se += __shfl_xor_sync(0xffffffffu, se, o);
    if (m < 24) battn[(h * 24 + l) * 24 + m] = e / se;
}

// ---------------------------------------------------------------------------
__global__ void topk_thresh(const float* __restrict__ battn, float* __restrict__ thr)
{
    const int h = blockIdx.x;
    __shared__ float buf[576];
    __shared__ float result;
    for (int e = threadIdx.x; e < 576; e += 256) buf[e] = battn[h * 576 + e];
    if (threadIdx.x == 0) result = 0.f;
    __syncthreads();
    for (int e = threadIdx.x; e < 576; e += 256) {
        float v = buf[e];
        int cg = 0, ce = 0;
        for (int x = 0; x < 576; x++) {
            cg += (buf[x] > v);
            ce += (buf[x] == v);
        }
        if (cg <= 128 && cg + ce >= 129) result = v;
    }
    __syncthreads();
    if (threadIdx.x == 0) thr[h] = result;
}

// ---------------------------------------------------------------------------
__global__ void build_lists(const float* __restrict__ battn,
                            const float* __restrict__ thr,
                            int* __restrict__ list, int* __restrict__ cnt)
{
    const int l = blockIdx.x, h = blockIdx.y;
    const int m = threadIdx.x;
    bool sel = (m < 24) && (battn[(h * 24 + l) * 24 + m] > thr[h]);
    unsigned msk = __ballot_sync(0xffffffffu, sel);
    int pos = __popc(msk & ((1u << m) - 1u));
    if (sel) list[(h * 24 + l) * 24 + pos] = m;
    if (m == 0) cnt[h * 24 + l] = __popc(msk);
}

// ---------------------------------------------------------------------------
// plan_work: build flat (pair, chunk) work-item table on device.
// ---------------------------------------------------------------------------
__global__ void plan_work(const int* __restrict__ cnt, int* __restrict__ items,
                          int* __restrict__ nch_arr, int* __restrict__ nwork)
{
    __shared__ int tot;
    const int tid = threadIdx.x;          // 288 threads
    if (tid == 0) tot = 0;
    __syncthreads();
    int nc = cnt[tid];
    int nch = (nc + CHUNK - 1) / CHUNK;
    nch_arr[tid] = nch;
    int pos = atomicAdd(&tot, nch);
    for (int c = 0; c < nch; c++)
        items[pos + c] = tid | (c << 16);
    __syncthreads();
    if (tid == 0) *nwork = tot;
}

// ---------------------------------------------------------------------------
// Block-sparse flash attention, split-KV: one CTA per (pair, chunk of <=4
// key blocks). Writes unnormalized partial O + per-row (m, den) to scratch.
// ---------------------------------------------------------------------------
#define AT_U32 68
#define AT_TILEB (128 * AT_U32 * 4)     // 34816
#define ATT_SMEM (6 * AT_TILEB)         // 208896

__global__ __launch_bounds__(256, 1) void attn_mma(
    const __nv_bfloat16* __restrict__ Qh, const __nv_bfloat16* __restrict__ Ql,
    const __nv_bfloat16* __restrict__ Kh, const __nv_bfloat16* __restrict__ Kl,
    const __nv_bfloat16* __restrict__ Vth, const __nv_bfloat16* __restrict__ Vtl,
    const int* __restrict__ list, const int* __restrict__ cnt,
    const int* __restrict__ items, const int* __restrict__ nwork,
    float* __restrict__ PO, float* __restrict__ PM, float* __restrict__ PD)
{
    if ((int)blockIdx.x >= *nwork) return;
    extern __shared__ char smem[];
    const int it = items[blockIdx.x];
    const int pair = it & 0xFFFF, ci = it >> 16;
    const int h = pair / 24, l = pair % 24;
    const int slot = pair * MAXCH + ci;
    const int nc = cnt[pair];
    const int bend = min(ci * CHUNK + CHUNK, nc);

    const int tid = threadIdx.x;
    const int lane = tid & 31, wid = tid >> 5;
    const int g = lane >> 2, th = lane & 3;
    const uint32_t sb = smem_u32(smem);

    // load Q hi/lo
#pragma unroll
    for (int t = 0; t < 2; t++) {
        const __nv_bfloat16* src = t ? Ql : Qh;
        uint32_t dst = sb + t * AT_TILEB;
#pragma unroll
        for (int u = 0; u < 8; u++) {
            int f = tid + 256 * u;
            int row = f >> 4, seg = f & 15;
            cp16(dst + row * 272 + seg * 16,
                 src + (size_t)(l * 128 + row) * DIM + h * 128 + seg * 8);
        }
    }
    CP_COMMIT();

    float oacc[16][4];
#pragma unroll
    for (int j = 0; j < 16; j++)
        oacc[j][0] = oacc[j][1] = oacc[j][2] = oacc[j][3] = 0.f;
    float m0 = NEG_BIG, m1 = NEG_BIG, den0 = 0.f, den1 = 0.f;

    const uint32_t* QhU = (const uint32_t*)smem;
    const uint32_t* QlU = QhU + AT_TILEB / 4;
    const uint32_t* KhU = QhU + 2 * (AT_TILEB / 4);
    const uint32_t* KlU = QhU + 3 * (AT_TILEB / 4);
    const uint32_t* VhU = QhU + 4 * (AT_TILEB / 4);
    const uint32_t* VlU = QhU + 5 * (AT_TILEB / 4);

    for (int b = ci * CHUNK; b < bend; b++) {
        const int mb = list[pair * 24 + b];
        __syncthreads();
#pragma unroll
        for (int u = 0; u < 8; u++) {
            int f = tid + 256 * u;
            int row = f >> 4, seg = f & 15;
            size_t ko = (size_t)(mb * 128 + row) * DIM + h * 128 + seg * 8;
            size_t vo = (size_t)(h * 128 + row) * S + mb * 128 + seg * 8;
            uint32_t so = row * 272 + seg * 16;
            cp16(sb + 2 * AT_TILEB + so, Kh + ko);
            cp16(sb + 3 * AT_TILEB + so, Kl + ko);
            cp16(sb + 4 * AT_TILEB + so, Vth + vo);
            cp16(sb + 5 * AT_TILEB + so, Vtl + vo);
        }
        CP_COMMIT();
        CP_WAIT(0);
        __syncthreads();

        // ---- S = Q K^T ----
        float sacc[16][4];
#pragma unroll
        for (int j = 0; j < 16; j++)
            sacc[j][0] = sacc[j][1] = sacc[j][2] = sacc[j][3] = 0.f;
#pragma unroll
        for (int ks = 0; ks < 8; ks++) {
            int aidx = (wid * 16 + g) * AT_U32 + ks * 8 + th;
            uint32_t ah0 = QhU[aidx], ah1 = QhU[aidx + 8 * AT_U32];
            uint32_t ah2 = QhU[aidx + 4], ah3 = QhU[aidx + 8 * AT_U32 + 4];
            uint32_t al0 = QlU[aidx], al1 = QlU[aidx + 8 * AT_U32];
            uint32_t al2 = QlU[aidx + 4], al3 = QlU[aidx + 8 * AT_U32 + 4];
#pragma unroll
            for (int j = 0; j < 16; j++) {
                int bidx = (j * 8 + g) * AT_U32 + ks * 8 + th;
                uint32_t bh0 = KhU[bidx], bh1 = KhU[bidx + 4];
                uint32_t bl0 = KlU[bidx], bl1 = KlU[bidx + 4];
                mma_bf16(sacc[j], ah0, ah1, ah2, ah3, bh0, bh1);
                mma_bf16(sacc[j], ah0, ah1, ah2, ah3, bl0, bl1);
                mma_bf16(sacc[j], al0, al1, al2, al3, bh0, bh1);
            }
        }

        // ---- online softmax ----
        float mx0 = NEG_BIG, mx1 = NEG_BIG;
#pragma unroll
        for (int j = 0; j < 16; j++) {
            sacc[j][0] *= SCALE; sacc[j][1] *= SCALE;
            sacc[j][2] *= SCALE; sacc[j][3] *= SCALE;
            mx0 = fmaxf(mx0, fmaxf(sacc[j][0], sacc[j][1]));
            mx1 = fmaxf(mx1, fmaxf(sacc[j][2], sacc[j][3]));
        }
        mx0 = fmaxf(mx0, __shfl_xor_sync(0xffffffffu, mx0, 1));
        mx0 = fmaxf(mx0, __shfl_xor_sync(0xffffffffu, mx0, 2));
        mx1 = fmaxf(mx1, __shfl_xor_sync(0xffffffffu, mx1, 1));
        mx1 = fmaxf(mx1, __shfl_xor_sync(0xffffffffu, mx1, 2));
        float nm0 = fmaxf(m0, mx0), nm1 = fmaxf(m1, mx1);
        float f0 = __expf(m0 - nm0), f1 = __expf(m1 - nm1);
        float rs0 = 0.f, rs1 = 0.f;
#pragma unroll
        for (int j = 0; j < 16; j++) {
            sacc[j][0] = __expf(sacc[j][0] - nm0);
            sacc[j][1] = __expf(sacc[j][1] - nm0);
            sacc[j][2] = __expf(sacc[j][2] - nm1);
            sacc[j][3] = __expf(sacc[j][3] - nm1);
            rs0 += sacc[j][0] + sacc[j][1];
            rs1 += sacc[j][2] + sacc[j][3];
        }
        rs0 += __shfl_xor_sync(0xffffffffu, rs0, 1);
        rs0 += __shfl_xor_sync(0xffffffffu, rs0, 2);
        rs1 += __shfl_xor_sync(0xffffffffu, rs1, 1);
        rs1 += __shfl_xor_sync(0xffffffffu, rs1, 2);
        den0 = den0 * f0 + rs0; m0 = nm0;
        den1 = den1 * f1 + rs1; m1 = nm1;
#pragma unroll
        for (int j = 0; j < 16; j++) {
            oacc[j][0] *= f0; oacc[j][1] *= f0;
            oacc[j][2] *= f1; oacc[j][3] *= f1;
        }

        // ---- O += P V ----
#pragma unroll
        for (int kk = 0; kk < 8; kk++) {
            float p00 = sacc[2 * kk][0],     p01 = sacc[2 * kk][1];
            float p10 = sacc[2 * kk][2],     p11 = sacc[2 * kk][3];
            float p20 = sacc[2 * kk + 1][0], p21 = sacc[2 * kk + 1][1];
            float p30 = sacc[2 * kk + 1][2], p31 = sacc[2 * kk + 1][3];
            uint32_t ph0 = pack2(p00, p01), ph1 = pack2(p10, p11);
            uint32_t ph2 = pack2(p20, p21), ph3 = pack2(p30, p31);
            __nv_bfloat162 h0 = *(__nv_bfloat162*)&ph0;
            __nv_bfloat162 h1 = *(__nv_bfloat162*)&ph1;
            __nv_bfloat162 h2 = *(__nv_bfloat162*)&ph2;
            __nv_bfloat162 h3 = *(__nv_bfloat162*)&ph3;
            uint32_t pl0 = pack2(p00 - __bfloat162float(h0.x), p01 - __bfloat162float(h0.y));
            uint32_t pl1 = pack2(p10 - __bfloat162float(h1.x), p11 - __bfloat162float(h1.y));
            uint32_t pl2 = pack2(p20 - __bfloat162float(h2.x), p21 - __bfloat162float(h2.y));
            uint32_t pl3 = pack2(p30 - __bfloat162float(h3.x), p31 - __bfloat162float(h3.y));
#pragma unroll
            for (int j = 0; j < 16; j++) {
                int bidx = (j * 8 + g) * AT_U32 + kk * 8 + th;
                uint32_t vh0 = VhU[bidx], vh1 = VhU[bidx + 4];
                uint32_t vl0 = VlU[bidx], vl1 = VlU[bidx + 4];
                mma_bf16(oacc[j], ph0, ph1, ph2, ph3, vh0, vh1);
                mma_bf16(oacc[j], ph0, ph1, ph2, ph3, vl0, vl1);
                mma_bf16(oacc[j], pl0, pl1, pl2, pl3, vh0, vh1);
            }
        }
    }

    // write partial (unnormalized O, per-row m/den)
    const int rl0 = wid * 16 + g, rl1 = rl0 + 8;
    if (th == 0) {
        PM[slot * 128 + rl0] = m0;  PD[slot * 128 + rl0] = den0;
        PM[slot * 128 + rl1] = m1;  PD[slot * 128 + rl1] = den1;
    }
    float* po = PO + (size_t)slot * 16384;
#pragma unroll
    for (int j = 0; j < 16; j++) {
        int col = j * 8 + 2 * th;
        *(float2*)(po + rl0 * 128 + col) = *(float2*)&oacc[j][0];
        *(float2*)(po + rl1 * 128 + col) = *(float2*)&oacc[j][2];
    }
}

// ---------------------------------------------------------------------------
// combine: merge chunk partials per pair; write bf16 hi/lo split output.
// grid = 288 pairs, 256 threads (thread = (row, col-half)).
// ---------------------------------------------------------------------------
__global__ __launch_bounds__(256) void combine_kernel(
    const float* __restrict__ PO, const float* __restrict__ PM,
    const float* __restrict__ PD, const int* __restrict__ nch_arr,
    __nv_bfloat16* __restrict__ OAh, __nv_bfloat16* __restrict__ OAl)
{
    const int pair = blockIdx.x;
    const int h = pair / 24, l = pair % 24;
    const int nch = nch_arr[pair];
    const int t = threadIdx.x;
    const int row = t >> 1;
    const int cb = (t & 1) * 64;
    const size_t gro = (size_t)(l * 128 + row) * DIM + h * 128 + cb;

    if (nch == 0) {
#pragma unroll
        for (int i = 0; i < 64; i += 2) {
            *(uint32_t*)(OAh + gro + i) = 0u;
            *(uint32_t*)(OAl + gro + i) = 0u;
        }
        return;
    }

    float M = NEG_BIG;
    for (int c = 0; c < nch; c++)
        M = fmaxf(M, PM[(pair * MAXCH + c) * 128 + row]);

    float acc[64];
#pragma unroll
    for (int i = 0; i < 64; i++) acc[i] = 0.f;
    float den = 0.f;
    for (int c = 0; c < nch; c++) {
        int slot = pair * MAXCH + c;
        float w = __expf(PM[slot * 128 + row] - M);
        den += w * PD[slot * 128 + row];
        const float* src = PO + (size_t)slot * 16384 + row * 128 + cb;
#pragma unroll
        for (int i = 0; i < 64; i += 4) {
            float4 v = *(const float4*)(src + i);
            acc[i + 0] += w * v.x; acc[i + 1] += w * v.y;
            acc[i + 2] += w * v.z; acc[i + 3] += w * v.w;
        }
    }
    float inv = den > 0.f ? 1.f / den : 0.f;
#pragma unroll
    for (int i = 0; i < 64; i += 2) {
        float v0 = acc[i] * inv, v1 = acc[i + 1] * inv;
        uint32_t hp = pack2(v0, v1);
        __nv_bfloat162 hb = *(__nv_bfloat162*)&hp;
        uint32_t lp = pack2(v0 - __bfloat162float(hb.x), v1 - __bfloat162float(hb.y));
        *(uint32_t*)(OAh + gro + i) = hp;
        *(uint32_t*)(OAl + gro + i) = lp;
    }
}

// ---------------------------------------------------------------------------
extern "C" void kernel_launch(void* const* d_in, const int* in_sizes, int n_in,
                              void* d_out, int out_size)
{
    const float* x  = (const float*)d_in[0];
    const float* wq = (const float*)d_in[1];
    const float* bq = (const float*)d_in[2];
    const float* wk = (const float*)d_in[3];
    const float* bk = (const float*)d_in[4];
    const float* wv = (const float*)d_in[5];
    const float* bv = (const float*)d_in[6];
    const float* wo = (const float*)d_in[7];
    const float* bo = (const float*)d_in[8];
    const float* gq = (const float*)d_in[9];
    const float* gk = (const float*)d_in[10];
    const float* fc = (const float*)d_in[11];
    const float* fs = (const float*)d_in[12];
    float* out = (float*)d_out;

    float *qp, *kp, *vp, *qwp, *kwp, *bap, *thp, *pop, *pmp, *pdp;
    int *lp, *cp, *itp, *nchp, *nwp;
    cudaGetSymbolAddress((void**)&qp, g_q);
    cudaGetSymbolAddress((void**)&kp, g_k);
    cudaGetSymbolAddress((void**)&vp, g_v);
    cudaGetSymbolAddress((void**)&qwp, g_qw);
    cudaGetSymbolAddress((void**)&kwp, g_kw);
    cudaGetSymbolAddress((void**)&bap, g_battn);
    cudaGetSymbolAddress((void**)&thp, g_thr);
    cudaGetSymbolAddress((void**)&lp, g_list);
    cudaGetSymbolAddress((void**)&cp, g_cnt);
    cudaGetSymbolAddress((void**)&itp, g_items);
    cudaGetSymbolAddress((void**)&nchp, g_nch);
    cudaGetSymbolAddress((void**)&nwp, g_nwork);
    cudaGetSymbolAddress((void**)&pop, g_po);
    cudaGetSymbolAddress((void**)&pmp, g_pm);
    cudaGetSymbolAddress((void**)&pdp, g_pd);

    __nv_bfloat16 *xh, *xl, *ah, *al;
    __nv_bfloat16 *wqh, *wql, *wkh, *wkl, *wvh, *wvl, *woh, *wol;
    __nv_bfloat16 *qh, *ql, *kh, *kl, *vth, *vtl;
    cudaGetSymbolAddress((void**)&xh, s_xh);
    cudaGetSymbolAddress((void**)&xl, s_xl);
    cudaGetSymbolAddress((void**)&ah, s_ah);
    cudaGetSymbolAddress((void**)&al, s_al);
    cudaGetSymbolAddress((void**)&wqh, s_wqh);
    cudaGetSymbolAddress((void**)&wql, s_wql);
    cudaGetSymbolAddress((void**)&wkh, s_wkh);
    cudaGetSymbolAddress((void**)&wkl, s_wkl);
    cudaGetSymbolAddress((void**)&wvh, s_wvh);
    cudaGetSymbolAddress((void**)&wvl, s_wvl);
    cudaGetSymbolAddress((void**)&woh, s_woh);
    cudaGetSymbolAddress((void**)&wol, s_wol);
    cudaGetSymbolAddress((void**)&qh, s_qh);
    cudaGetSymbolAddress((void**)&ql, s_ql);
    cudaGetSymbolAddress((void**)&kh, s_kh);
    cudaGetSymbolAddress((void**)&kl, s_kl);
    cudaGetSymbolAddress((void**)&vth, s_vth);
    cudaGetSymbolAddress((void**)&vtl, s_vtl);

    cudaFuncSetAttribute(gemm_mma, cudaFuncAttributeMaxDynamicSharedMemorySize, GEMM_SMEM);
    cudaFuncSetAttribute(attn_mma, cudaFuncAttributeMaxDynamicSharedMemorySize, ATT_SMEM);

    // splits (x + weights)
    split_kernel<<<(S * DIM) / 256, 256>>>(x, xh, xl);
    split_kernel<<<(DIM * DIM) / 256, 256>>>(wq, wqh, wql);
    split_kernel<<<(DIM * DIM) / 256, 256>>>(wk, wkh, wkl);
    split_kernel<<<(DIM * DIM) / 256, 256>>>(wv, wvh, wvl);
    split_kernel<<<(DIM * DIM) / 256, 256>>>(wo, woh, wol);

    // Q/K/V projections (z-batched)
    gemm_mma<<<dim3(12, 24, 3), 256, GEMM_SMEM>>>(
        xh, xl, wqh, wql, wkh, wkl, wvh, wvl, bq, bk, bv, qp, kp, vp);

    norm_rope_kernel<<<dim3(S, 2), 256>>>(qp, kp, qh, ql, kh, kl, gq, gk, fc, fs);
    pool_mean<<<dim3(NB, 2), 256>>>(qp, kp, qwp, kwp);
    draft_scores<<<dim3(H, NB), 32>>>(qwp, kwp, bap);
    topk_thresh<<<H, 256>>>(bap, thp);
    build_lists<<<dim3(NB, H), 32>>>(bap, thp, lp, cp);
    plan_work<<<1, NPAIR>>>(cp, itp, nchp, nwp);

    vt_split<<<dim3(S / 32, DIM / 32), 256>>>(vp, vth, vtl);

    // split-KV attention: fixed over-provisioned grid, early exit past nwork
    attn_mma<<<NSLOT, 256, ATT_SMEM>>>(qh, ql, kh, kl, vth, vtl,
                                       lp, cp, itp, nwp, pop, pmp, pdp);
    combine_kernel<<<NPAIR, 256>>>(pop, pmp, pdp, nchp, ah, al);

    // O projection
    gemm_mma<<<dim3(12, 24, 1), 256, GEMM_SMEM>>>(
        ah, al, woh, wol, woh, wol, woh, wol, bo, bo, bo, out, out, out);
}

// round 14
// speedup vs baseline: 1.0640x; 1.0640x over previous
#include <cuda_runtime.h>
#include <cuda_bf16.h>
#include <cstdint>

#define S 3072
#define DIM 1536
#define H 12
#define NB 24
#define SCALE 0.08838834764831845f   // 1/sqrt(128)
#define NEG_BIG (-1e30f)
#define NPAIR (H * NB)                // 288

// ---------------- scratch (device globals; no allocation allowed) ----------
__device__ float g_q[S * DIM];
__device__ float g_k[S * DIM];
__device__ float g_v[S * DIM];
__device__ float g_qw[NB * DIM];
__device__ float g_kw[NB * DIM];
__device__ float g_battn[H * NB * NB];
__device__ float g_thr[H];
__device__ int   g_list[H * NB * NB];
__device__ int   g_cnt[NPAIR];
__device__ int   g_order[NPAIR];

// bf16 hi/lo splits
__device__ __nv_bfloat16 s_xh[S * DIM],  s_xl[S * DIM];
__device__ __nv_bfloat16 s_ah[S * DIM],  s_al[S * DIM];
__device__ __nv_bfloat16 s_wqh[DIM * DIM], s_wql[DIM * DIM];
__device__ __nv_bfloat16 s_wkh[DIM * DIM], s_wkl[DIM * DIM];
__device__ __nv_bfloat16 s_wvh[DIM * DIM], s_wvl[DIM * DIM];
__device__ __nv_bfloat16 s_woh[DIM * DIM], s_wol[DIM * DIM];
__device__ __nv_bfloat16 s_qh[S * DIM], s_ql[S * DIM];
__device__ __nv_bfloat16 s_kh[S * DIM], s_kl[S * DIM];
__device__ __nv_bfloat16 s_vth[DIM * S], s_vtl[DIM * S];   // transposed [d][t]

// ---------------------------------------------------------------------------
__device__ __forceinline__ uint32_t smem_u32(const void* p) {
    uint32_t a;
    asm("{ .reg .u64 t; cvta.to.shared.u64 t, %1; cvt.u32.u64 %0, t; }"
        : "=r"(a) : "l"(p));
    return a;
}
__device__ __forceinline__ void cp16(uint32_t dst, const void* src) {
    asm volatile("cp.async.cg.shared.global [%0], [%1], 16;" :: "r"(dst), "l"(src));
}
#define CP_COMMIT() asm volatile("cp.async.commit_group;" ::: "memory")
#define CP_WAIT(n)  asm volatile("cp.async.wait_group %0;" :: "n"(n) : "memory")

__device__ __forceinline__ void mma_bf16(float* c, uint32_t a0, uint32_t a1,
                                         uint32_t a2, uint32_t a3,
                                         uint32_t b0, uint32_t b1) {
    asm volatile(
        "mma.sync.aligned.m16n8k16.row.col.f32.bf16.bf16.f32 "
        "{%0,%1,%2,%3}, {%4,%5,%6,%7}, {%8,%9}, {%0,%1,%2,%3};"
        : "+f"(c[0]), "+f"(c[1]), "+f"(c[2]), "+f"(c[3])
        : "r"(a0), "r"(a1), "r"(a2), "r"(a3), "r"(b0), "r"(b1));
}
__device__ __forceinline__ void ldsm_x4(uint32_t& r0, uint32_t& r1,
                                        uint32_t& r2, uint32_t& r3, uint32_t a) {
    asm volatile("ldmatrix.sync.aligned.m8n8.x4.shared.b16 {%0,%1,%2,%3}, [%4];"
                 : "=r"(r0), "=r"(r1), "=r"(r2), "=r"(r3) : "r"(a));
}
__device__ __forceinline__ uint32_t pack2(float x, float y) {
    __nv_bfloat162 t = __floats2bfloat162_rn(x, y);
    return *(uint32_t*)&t;
}

// ---------------------------------------------------------------------------
__global__ __launch_bounds__(256) void split_kernel(
    const float* __restrict__ X, __nv_bfloat16* __restrict__ Hh,
    __nv_bfloat16* __restrict__ Hl)
{
    int i = blockIdx.x * 256 + threadIdx.x;
    float v = X[i];
    __nv_bfloat16 h = __float2bfloat16(v);
    Hh[i] = h;
    Hl[i] = __float2bfloat16(v - __bfloat162float(h));
}

// ---------------------------------------------------------------------------
__global__ __launch_bounds__(256) void vt_split(
    const float* __restrict__ V, __nv_bfloat16* __restrict__ Th,
    __nv_bfloat16* __restrict__ Tl)
{
    __shared__ float tile[32][33];
    const int t0 = blockIdx.x * 32, d0 = blockIdx.y * 32;
    const int tx = threadIdx.x & 31, ty = threadIdx.x >> 5;
#pragma unroll
    for (int i = 0; i < 4; i++)
        tile[ty + 8 * i][tx] = V[(size_t)(t0 + ty + 8 * i) * DIM + d0 + tx];
    __syncthreads();
#pragma unroll
    for (int i = 0; i < 4; i++) {
        float v = tile[tx][ty + 8 * i];
        __nv_bfloat16 h = __float2bfloat16(v);
        size_t o = (size_t)(d0 + ty + 8 * i) * S + t0 + tx;
        Th[o] = h;
        Tl[o] = __float2bfloat16(v - __bfloat162float(h));
    }
}

// ---------------------------------------------------------------------------
// mma.sync GEMM, bf16-split 3-product, 3-stage pipeline, ldmatrix frags.
// ---------------------------------------------------------------------------
#define TILEB 18432                   // 128 rows * 144B
#define STAGEB (4 * TILEB)
#define GEMM_SMEM (3 * STAGEB)

__global__ __launch_bounds__(256, 1) void gemm_mma(
    const __nv_bfloat16* __restrict__ Ah, const __nv_bfloat16* __restrict__ Al,
    const __nv_bfloat16* __restrict__ Wh0, const __nv_bfloat16* __restrict__ Wl0,
    const __nv_bfloat16* __restrict__ Wh1, const __nv_bfloat16* __restrict__ Wl1,
    const __nv_bfloat16* __restrict__ Wh2, const __nv_bfloat16* __restrict__ Wl2,
    const float* __restrict__ b0, const float* __restrict__ b1,
    const float* __restrict__ b2,
    float* __restrict__ C0, float* __restrict__ C1, float* __restrict__ C2)
{
    extern __shared__ char smem[];
    const int z = blockIdx.z;
    const __nv_bfloat16* Wh = z == 0 ? Wh0 : (z == 1 ? Wh1 : Wh2);
    const __nv_bfloat16* Wl = z == 0 ? Wl0 : (z == 1 ? Wl1 : Wl2);
    const float* bias = z == 0 ? b0 : (z == 1 ? b1 : b2);
    float* C = z == 0 ? C0 : (z == 1 ? C1 : C2);

    const int n0 = blockIdx.x * 128;
    const int m0 = blockIdx.y * 128;
    const int tid = threadIdx.x;
    const int lane = tid & 31, wid = tid >> 5;
    const int warp_m = wid & 3, warp_n = wid >> 2;
    const int g = lane >> 2, th = lane & 3;
    const int lidx = lane >> 3, lrow = lane & 7;

    const uint32_t sbase = smem_u32(smem);
    // ldmatrix per-lane offsets (bytes): A frag (x4 = full m16k16), B frag (x4 = two n8k16)
    const uint32_t ga_off = (uint32_t)(warp_m * 32 + lrow + ((lane >> 3) & 1) * 8) * 144
                          + ((lane >> 4) & 1) * 16;
    const uint32_t gb_off = (uint32_t)(warp_n * 64 + lrow + (lidx >> 1) * 8) * 144
                          + (lidx & 1) * 16;

    auto load_stage = [&](int stage, int c) {
        const __nv_bfloat16* srcs[4] = {
            Ah + (size_t)m0 * DIM + c * 64,
            Al + (size_t)m0 * DIM + c * 64,
            Wh + (size_t)n0 * DIM + c * 64,
            Wl + (size_t)n0 * DIM + c * 64 };
        uint32_t stb = sbase + stage * STAGEB;
#pragma unroll
        for (int t = 0; t < 4; t++) {
#pragma unroll
            for (int u = 0; u < 4; u++) {
                int f = tid + 256 * u;
                int row = f >> 3, seg = f & 7;
                cp16(stb + t * TILEB + row * 144 + seg * 16,
                     srcs[t] + (size_t)row * DIM + seg * 8);
            }
        }
    };

    float acc[2][8][4];
#pragma unroll
    for (int i = 0; i < 2; i++)
#pragma unroll
        for (int j = 0; j < 8; j++)
#pragma unroll
            for (int r = 0; r < 4; r++) acc[i][j][r] = 0.f;

    load_stage(0, 0); CP_COMMIT();
    load_stage(1, 1); CP_COMMIT();

    for (int c = 0; c < 24; c++) {
        if (c < 23) { CP_WAIT(1); } else { CP_WAIT(0); }
        __syncthreads();

        const uint32_t stg = sbase + (c % 3) * STAGEB;
        const uint32_t sAh = stg, sAl = stg + TILEB;
        const uint32_t sWh = stg + 2 * TILEB, sWl = stg + 3 * TILEB;

#pragma unroll
        for (int ks = 0; ks < 4; ks++) {
            uint32_t ah[2][4], al[2][4];
#pragma unroll
            for (int mt = 0; mt < 2; mt++) {
                ldsm_x4(ah[mt][0], ah[mt][1], ah[mt][2], ah[mt][3],
                        sAh + ga_off + mt * 2304 + ks * 32);
                ldsm_x4(al[mt][0], al[mt][1], al[mt][2], al[mt][3],
                        sAl + ga_off + mt * 2304 + ks * 32);
            }
#pragma unroll
            for (int jp = 0; jp < 4; jp++) {
                uint32_t bh0, bh1, bh2, bh3, bl0, bl1, bl2, bl3;
                ldsm_x4(bh0, bh1, bh2, bh3, sWh + gb_off + jp * 2304 + ks * 32);
                ldsm_x4(bl0, bl1, bl2, bl3, sWl + gb_off + jp * 2304 + ks * 32);
#pragma unroll
                for (int mt = 0; mt < 2; mt++) {
                    mma_bf16(acc[mt][2 * jp], ah[mt][0], ah[mt][1], ah[mt][2], ah[mt][3], bh0, bh1);
                    mma_bf16(acc[mt][2 * jp], ah[mt][0], ah[mt][1], ah[mt][2], ah[mt][3], bl0, bl1);
                    mma_bf16(acc[mt][2 * jp], al[mt][0], al[mt][1], al[mt][2], al[mt][3], bh0, bh1);
                    mma_bf16(acc[mt][2 * jp + 1], ah[mt][0], ah[mt][1], ah[mt][2], ah[mt][3], bh2, bh3);
                    mma_bf16(acc[mt][2 * jp + 1], ah[mt][0], ah[mt][1], ah[mt][2], ah[mt][3], bl2, bl3);
                    mma_bf16(acc[mt][2 * jp + 1], al[mt][0], al[mt][1], al[mt][2], al[mt][3], bh2, bh3);
                }
            }
        }
        if (c + 2 < 24) { load_stage((c + 2) % 3, c + 2); CP_COMMIT(); }
        __syncthreads();
    }

#pragma unroll
    for (int mt = 0; mt < 2; mt++) {
        int r = m0 + warp_m * 32 + mt * 16 + g;
#pragma unroll
        for (int j = 0; j < 8; j++) {
            int col = n0 + warp_n * 64 + j * 8 + th * 2;
            float bx = bias[col], by = bias[col + 1];
            float2 o0 = { acc[mt][j][0] + bx, acc[mt][j][1] + by };
            float2 o1 = { acc[mt][j][2] + bx, acc[mt][j][3] + by };
            *(float2*)(C + (size_t)r * DIM + col) = o0;
            *(float2*)(C + (size_t)(r + 8) * DIM + col) = o1;
        }
    }
}

// ---------------------------------------------------------------------------
// RMSNorm + RoPE, fused bf16 hi/lo split output
// ---------------------------------------------------------------------------
__global__ __launch_bounds__(256) void norm_rope_kernel(
    float* __restrict__ Xq, float* __restrict__ Xk,
    __nv_bfloat16* __restrict__ Qh, __nv_bfloat16* __restrict__ Ql,
    __nv_bfloat16* __restrict__ Kh, __nv_bfloat16* __restrict__ Kl,
    const float* __restrict__ gq, const float* __restrict__ gk,
    const float* __restrict__ fc, const float* __restrict__ fs)
{
    const int s = blockIdx.x;
    float* X = blockIdx.y ? Xk : Xq;
    __nv_bfloat16* Oh = blockIdx.y ? Kh : Qh;
    __nv_bfloat16* Ol = blockIdx.y ? Kl : Ql;
    const float* g = blockIdx.y ? gk : gq;
    float* row = X + (size_t)s * 1536;
    const int tid = threadIdx.x;

    float ss = 0.f;
#pragma unroll
    for (int c = 0; c < 6; c++) {
        float v = row[tid + 256 * c];
        ss += v * v;
    }
#pragma unroll
    for (int o = 16; o >= 1; o >>= 1)
        ss += __shfl_xor_sync(0xffffffffu, ss, o);
    __shared__ float red[8];
    if ((tid & 31) == 0) red[tid >> 5] = ss;
    __syncthreads();
    float tot = 0.f;
#pragma unroll
    for (int w = 0; w < 8; w++) tot += red[w];
    float scale = rsqrtf(tot * (1.f / 1536.f) + 1e-5f);

#pragma unroll
    for (int u = 0; u < 3; u++) {
        int p = tid + 256 * u;
        int i = p & 63;
        float c = fc[s * 64 + i];
        float sn = fs[s * 64 + i];
        float x0 = row[2 * p] * scale * g[2 * p];
        float x1 = row[2 * p + 1] * scale * g[2 * p + 1];
        float y0 = x0 * c - x1 * sn;
        float y1 = x0 * sn + x1 * c;
        row[2 * p]     = y0;
        row[2 * p + 1] = y1;
        size_t o = (size_t)s * 1536 + 2 * p;
        __nv_bfloat16 h0 = __float2bfloat16(y0);
        __nv_bfloat16 h1 = __float2bfloat16(y1);
        Oh[o] = h0;     Oh[o + 1] = h1;
        Ol[o] = __float2bfloat16(y0 - __bfloat162float(h0));
        Ol[o + 1] = __float2bfloat16(y1 - __bfloat162float(h1));
    }
}

// ---------------------------------------------------------------------------
__global__ __launch_bounds__(256) void pool_mean(
    const float* __restrict__ Q, const float* __restrict__ Kx,
    float* __restrict__ qw, float* __restrict__ kw)
{
    const int nb = blockIdx.x;
    const float* X = blockIdx.y ? Kx : Q;
    float* Wo = blockIdx.y ? kw : qw;
    const int tid = threadIdx.x;
    float acc[6] = {0, 0, 0, 0, 0, 0};
    for (int t = 0; t < 128; t++) {
        const float* row = X + (size_t)(nb * 128 + t) * 1536;
#pragma unroll
        for (int c = 0; c < 6; c++) acc[c] += row[tid + 256 * c];
    }
#pragma unroll
    for (int c = 0; c < 6; c++)
        Wo[nb * 1536 + tid + 256 * c] = acc[c] * (1.f / 128.f);
}

// ---------------------------------------------------------------------------
__global__ void draft_scores(const float* __restrict__ qw,
                             const float* __restrict__ kw,
                             float* __restrict__ battn)
{
    const int h = blockIdx.x, l = blockIdx.y;
    const int m = threadIdx.x;
    float sc = NEG_BIG;
    if (m < 24) {
        int rl = l >> 2, cl = l & 3, rm = m >> 2, cm = m & 3;
        bool ok = (rm >= rl - 3) && (rm <= rl + 2) && (cm >= cl - 3) && (cm <= cl + 2);
        if (ok) {
            float sum = 0.f;
            const float* qr = qw + l * 1536 + h * 128;
            const float* kr = kw + m * 1536 + h * 128;
#pragma unroll 8
            for (int d = 0; d < 128; d++) sum += qr[d] * kr[d];
            sc = sum * SCALE;
        }
    }
    float mx = sc;
#pragma unroll
    for (int o = 16; o >= 1; o >>= 1)
        mx = fmaxf(mx, __shfl_xor_sync(0xffffffffu, mx, o));
    float e = __expf(sc - mx);
    float se = e;
#pragma unroll
    for (int o = 16; o >= 1; o >>= 1)
        se += __shfl_xor_sync(0xffffffffu, se, o);
    if (m < 24) battn[(h * 24 + l) * 24 + m] = e / se;
}

// ---------------------------------------------------------------------------
__global__ void topk_thresh(const float* __restrict__ battn, float* __restrict__ thr)
{
    const int h = blockIdx.x;
    __shared__ float buf[576];
    __shared__ float result;
    for (int e = threadIdx.x; e < 576; e += 256) buf[e] = battn[h * 576 + e];
    if (threadIdx.x == 0) result = 0.f;
    __syncthreads();
    for (int e = threadIdx.x; e < 576; e += 256) {
        float v = buf[e];
        int cg = 0, ce = 0;
        for (int x = 0; x < 576; x++) {
            cg += (buf[x] > v);
            ce += (buf[x] == v);
        }
        if (cg <= 128 && cg + ce >= 129) result = v;
    }
    __syncthreads();
    if (threadIdx.x == 0) thr[h] = result;
}

// ---------------------------------------------------------------------------
__global__ void build_lists(const float* __restrict__ battn,
                            const float* __restrict__ thr,
                            int* __restrict__ list, int* __restrict__ cnt)
{
    const int l = blockIdx.x, h = blockIdx.y;
    const int m = threadIdx.x;
    bool sel = (m < 24) && (battn[(h * 24 + l) * 24 + m] > thr[h]);
    unsigned msk = __ballot_sync(0xffffffffu, sel);
    int pos = __popc(msk & ((1u << m) - 1u));
    if (sel) list[(h * 24 + l) * 24 + pos] = m;
    if (m == 0) cnt[h * 24 + l] = __popc(msk);
}

// ---------------------------------------------------------------------------
// LPT ordering: counting-sort the 288 pairs by descending block count.
// ---------------------------------------------------------------------------
__global__ void order_pairs(const int* __restrict__ cnt, int* __restrict__ order)
{
    __shared__ int bucket[32];
    __shared__ int base[32];
    const int tid = threadIdx.x;
    if (tid < 32) bucket[tid] = 0;
    __syncthreads();
    int nc = cnt[tid];
    atomicAdd(&bucket[nc], 1);
    __syncthreads();
    if (tid == 0) {
        int acc = 0;
        for (int v = 31; v >= 0; v--) { base[v] = acc; acc += bucket[v]; }
    }
    __syncthreads();
    int pos = atomicAdd(&base[nc], 1);
    order[pos] = tid;
}

// ---------------------------------------------------------------------------
// Block-sparse flash attention via mma.sync + ldmatrix, LPT pair order.
// ---------------------------------------------------------------------------
#define AT_U32 68
#define AT_TILEB (128 * AT_U32 * 4)     // 34816
#define ATT_SMEM (6 * AT_TILEB)         // 208896

__global__ __launch_bounds__(256, 1) void attn_mma(
    const __nv_bfloat16* __restrict__ Qh, const __nv_bfloat16* __restrict__ Ql,
    const __nv_bfloat16* __restrict__ Kh, const __nv_bfloat16* __restrict__ Kl,
    const __nv_bfloat16* __restrict__ Vth, const __nv_bfloat16* __restrict__ Vtl,
    const int* __restrict__ list, const int* __restrict__ cnt,
    const int* __restrict__ order,
    __nv_bfloat16* __restrict__ OAh, __nv_bfloat16* __restrict__ OAl)
{
    extern __shared__ char smem[];
    const int pair = order[blockIdx.x];
    const int h = pair / 24, l = pair % 24;
    const int tid = threadIdx.x;
    const int lane = tid & 31, wid = tid >> 5;
    const int g = lane >> 2, th = lane & 3;
    const int lidx = lane >> 3, lrow = lane & 7;
    const uint32_t sb = smem_u32(smem);
    const uint32_t sQh = sb, sQl = sb + AT_TILEB;
    const uint32_t sKh = sb + 2 * AT_TILEB, sKl = sb + 3 * AT_TILEB;
    const uint32_t sVh = sb + 4 * AT_TILEB, sVl = sb + 5 * AT_TILEB;

    // ldmatrix per-lane byte offsets
    const uint32_t a_off = (uint32_t)(wid * 16 + lrow + ((lane >> 3) & 1) * 8) * 272
                         + ((lane >> 4) & 1) * 16;
    const uint32_t b_off = (uint32_t)(lrow + (lidx >> 1) * 8) * 272 + (lidx & 1) * 16;

    // load Q hi/lo once
#pragma unroll
    for (int t = 0; t < 2; t++) {
        const __nv_bfloat16* src = t ? Ql : Qh;
        uint32_t dst = sb + t * AT_TILEB;
#pragma unroll
        for (int u = 0; u < 8; u++) {
            int f = tid + 256 * u;
            int row = f >> 4, seg = f & 15;
            cp16(dst + row * 272 + seg * 16,
                 src + (size_t)(l * 128 + row) * DIM + h * 128 + seg * 8);
        }
    }
    CP_COMMIT();

    float oacc[16][4];
#pragma unroll
    for (int j = 0; j < 16; j++)
        oacc[j][0] = oacc[j][1] = oacc[j][2] = oacc[j][3] = 0.f;
    float m0 = NEG_BIG, m1 = NEG_BIG, den0 = 0.f, den1 = 0.f;

    const int nc = cnt[pair];
    for (int b = 0; b < nc; b++) {
        const int mb = list[pair * 24 + b];
        __syncthreads();
#pragma unroll
        for (int u = 0; u < 8; u++) {
            int f = tid + 256 * u;
            int row = f >> 4, seg = f & 15;
            size_t ko = (size_t)(mb * 128 + row) * DIM + h * 128 + seg * 8;
            size_t vo = (size_t)(h * 128 + row) * S + mb * 128 + seg * 8;
            uint32_t so = row * 272 + seg * 16;
            cp16(sKh + so, Kh + ko);
            cp16(sKl + so, Kl + ko);
            cp16(sVh + so, Vth + vo);
            cp16(sVl + so, Vtl + vo);
        }
        CP_COMMIT();
        CP_WAIT(0);
        __syncthreads();

        // ---- S = Q K^T (3-product split, ldmatrix frags) ----
        float sacc[16][4];
#pragma unroll
        for (int j = 0; j < 16; j++)
            sacc[j][0] = sacc[j][1] = sacc[j][2] = sacc[j][3] = 0.f;
#pragma unroll
        for (int ks = 0; ks < 8; ks++) {
            uint32_t ah0, ah1, ah2, ah3, al0, al1, al2, al3;
            ldsm_x4(ah0, ah1, ah2, ah3, sQh + a_off + ks * 32);
            ldsm_x4(al0, al1, al2, al3, sQl + a_off + ks * 32);
#pragma unroll
            for (int jp = 0; jp < 8; jp++) {
                uint32_t kh0, kh1, kh2, kh3, kl0, kl1, kl2, kl3;
                ldsm_x4(kh0, kh1, kh2, kh3, sKh + b_off + jp * 4352 + ks * 32);
                ldsm_x4(kl0, kl1, kl2, kl3, sKl + b_off + jp * 4352 + ks * 32);
                mma_bf16(sacc[2 * jp], ah0, ah1, ah2, ah3, kh0, kh1);
                mma_bf16(sacc[2 * jp], ah0, ah1, ah2, ah3, kl0, kl1);
                mma_bf16(sacc[2 * jp], al0, al1, al2, al3, kh0, kh1);
                mma_bf16(sacc[2 * jp + 1], ah0, ah1, ah2, ah3, kh2, kh3);
                mma_bf16(sacc[2 * jp + 1], ah0, ah1, ah2, ah3, kl2, kl3);
                mma_bf16(sacc[2 * jp + 1], al0, al1, al2, al3, kh2, kh3);
            }
        }

        // ---- online softmax ----
        float mx0 = NEG_BIG, mx1 = NEG_BIG;
#pragma unroll
        for (int j = 0; j < 16; j++) {
            sacc[j][0] *= SCALE; sacc[j][1] *= SCALE;
            sacc[j][2] *= SCALE; sacc[j][3] *= SCALE;
            mx0 = fmaxf(mx0, fmaxf(sacc[j][0], sacc[j][1]));
            mx1 = fmaxf(mx1, fmaxf(sacc[j][2], sacc[j][3]));
        }
        mx0 = fmaxf(mx0, __shfl_xor_sync(0xffffffffu, mx0, 1));
        mx0 = fmaxf(mx0, __shfl_xor_sync(0xffffffffu, mx0, 2));
        mx1 = fmaxf(mx1, __shfl_xor_sync(0xffffffffu, mx1, 1));
        mx1 = fmaxf(mx1, __shfl_xor_sync(0xffffffffu, mx1, 2));
        float nm0 = fmaxf(m0, mx0), nm1 = fmaxf(m1, mx1);
        float f0 = __expf(m0 - nm0), f1 = __expf(m1 - nm1);
        float rs0 = 0.f, rs1 = 0.f;
#pragma unroll
        for (int j = 0; j < 16; j++) {
            sacc[j][0] = __expf(sacc[j][0] - nm0);
            sacc[j][1] = __expf(sacc[j][1] - nm0);
            sacc[j][2] = __expf(sacc[j][2] - nm1);
            sacc[j][3] = __expf(sacc[j][3] - nm1);
            rs0 += sacc[j][0] + sacc[j][1];
            rs1 += sacc[j][2] + sacc[j][3];
        }
        rs0 += __shfl_xor_sync(0xffffffffu, rs0, 1);
        rs0 += __shfl_xor_sync(0xffffffffu, rs0, 2);
        rs1 += __shfl_xor_sync(0xffffffffu, rs1, 1);
        rs1 += __shfl_xor_sync(0xffffffffu, rs1, 2);
        den0 = den0 * f0 + rs0; m0 = nm0;
        den1 = den1 * f1 + rs1; m1 = nm1;
#pragma unroll
        for (int j = 0; j < 16; j++) {
            oacc[j][0] *= f0; oacc[j][1] *= f0;
            oacc[j][2] *= f1; oacc[j][3] *= f1;
        }

        // ---- O += P V (P from registers, hi/lo split; ldmatrix V frags) ----
#pragma unroll
        for (int kk = 0; kk < 8; kk++) {
            float p00 = sacc[2 * kk][0],     p01 = sacc[2 * kk][1];
            float p10 = sacc[2 * kk][2],     p11 = sacc[2 * kk][3];
            float p20 = sacc[2 * kk + 1][0], p21 = sacc[2 * kk + 1][1];
            float p30 = sacc[2 * kk + 1][2], p31 = sacc[2 * kk + 1][3];
            uint32_t ph0 = pack2(p00, p01), ph1 = pack2(p10, p11);
            uint32_t ph2 = pack2(p20, p21), ph3 = pack2(p30, p31);
            __nv_bfloat162 h0 = *(__nv_bfloat162*)&ph0;
            __nv_bfloat162 h1 = *(__nv_bfloat162*)&ph1;
            __nv_bfloat162 h2 = *(__nv_bfloat162*)&ph2;
            __nv_bfloat162 h3 = *(__nv_bfloat162*)&ph3;
            uint32_t pl0 = pack2(p00 - __bfloat162float(h0.x), p01 - __bfloat162float(h0.y));
            uint32_t pl1 = pack2(p10 - __bfloat162float(h1.x), p11 - __bfloat162float(h1.y));
            uint32_t pl2 = pack2(p20 - __bfloat162float(h2.x), p21 - __bfloat162float(h2.y));
            uint32_t pl3 = pack2(p30 - __bfloat162float(h3.x), p31 - __bfloat162float(h3.y));
#pragma unroll
            for (int jp = 0; jp < 8; jp++) {
                uint32_t vh0, vh1, vh2, vh3, vl0, vl1, vl2, vl3;
                ldsm_x4(vh0, vh1, vh2, vh3, sVh + b_off + jp * 4352 + kk * 32);
                ldsm_x4(vl0, vl1, vl2, vl3, sVl + b_off + jp * 4352 + kk * 32);
                mma_bf16(oacc[2 * jp], ph0, ph1, ph2, ph3, vh0, vh1);
                mma_bf16(oacc[2 * jp], ph0, ph1, ph2, ph3, vl0, vl1);
                mma_bf16(oacc[2 * jp], pl0, pl1, pl2, pl3, vh0, vh1);
                mma_bf16(oacc[2 * jp + 1], ph0, ph1, ph2, ph3, vh2, vh3);
                mma_bf16(oacc[2 * jp + 1], ph0, ph1, ph2, ph3, vl2, vl3);
                mma_bf16(oacc[2 * jp + 1], pl0, pl1, pl2, pl3, vh2, vh3);
            }
        }
    }

    // epilogue: normalize + bf16 hi/lo split write
    float inv0 = den0 > 0.f ? 1.f / den0 : 0.f;
    float inv1 = den1 > 0.f ? 1.f / den1 : 0.f;
    const int r0 = l * 128 + wid * 16 + g, r1 = r0 + 8;
#pragma unroll
    for (int j = 0; j < 16; j++) {
        int col = h * 128 + j * 8 + 2 * th;
        float v00 = oacc[j][0] * inv0, v01 = oacc[j][1] * inv0;
        float v10 = oacc[j][2] * inv1, v11 = oacc[j][3] * inv1;
        uint32_t h0 = pack2(v00, v01);
        uint32_t h1 = pack2(v10, v11);
        __nv_bfloat162 b0 = *(__nv_bfloat162*)&h0;
        __nv_bfloat162 b1 = *(__nv_bfloat162*)&h1;
        uint32_t l0 = pack2(v00 - __bfloat162float(b0.x), v01 - __bfloat162float(b0.y));
        uint32_t l1 = pack2(v10 - __bfloat162float(b1.x), v11 - __bfloat162float(b1.y));
        *(uint32_t*)(OAh + (size_t)r0 * DIM + col) = h0;
        *(uint32_t*)(OAl + (size_t)r0 * DIM + col) = l0;
        *(uint32_t*)(OAh + (size_t)r1 * DIM + col) = h1;
        *(uint32_t*)(OAl + (size_t)r1 * DIM + col) = l1;
    }
}

// ---------------------------------------------------------------------------
extern "C" void kernel_launch(void* const* d_in, const int* in_sizes, int n_in,
                              void* d_out, int out_size)
{
    const float* x  = (const float*)d_in[0];
    const float* wq = (const float*)d_in[1];
    const float* bq = (const float*)d_in[2];
    const float* wk = (const float*)d_in[3];
    const float* bk = (const float*)d_in[4];
    const float* wv = (const float*)d_in[5];
    const float* bv = (const float*)d_in[6];
    const float* wo = (const float*)d_in[7];
    const float* bo = (const float*)d_in[8];
    const float* gq = (const float*)d_in[9];
    const float* gk = (const float*)d_in[10];
    const float* fc = (const float*)d_in[11];
    const float* fs = (const float*)d_in[12];
    float* out = (float*)d_out;

    float *qp, *kp, *vp, *qwp, *kwp, *bap, *thp;
    int *lp, *cp, *op;
    cudaGetSymbolAddress((void**)&qp, g_q);
    cudaGetSymbolAddress((void**)&kp, g_k);
    cudaGetSymbolAddress((void**)&vp, g_v);
    cudaGetSymbolAddress((void**)&qwp, g_qw);
    cudaGetSymbolAddress((void**)&kwp, g_kw);
    cudaGetSymbolAddress((void**)&bap, g_battn);
    cudaGetSymbolAddress((void**)&thp, g_thr);
    cudaGetSymbolAddress((void**)&lp, g_list);
    cudaGetSymbolAddress((void**)&cp, g_cnt);
    cudaGetSymbolAddress((void**)&op, g_order);

    __nv_bfloat16 *xh, *xl, *ah, *al;
    __nv_bfloat16 *wqh, *wql, *wkh, *wkl, *wvh, *wvl, *woh, *wol;
    __nv_bfloat16 *qh, *ql, *kh, *kl, *vth, *vtl;
    cudaGetSymbolAddress((void**)&xh, s_xh);
    cudaGetSymbolAddress((void**)&xl, s_xl);
    cudaGetSymbolAddress((void**)&ah, s_ah);
    cudaGetSymbolAddress((void**)&al, s_al);
    cudaGetSymbolAddress((void**)&wqh, s_wqh);
    cudaGetSymbolAddress((void**)&wql, s_wql);
    cudaGetSymbolAddress((void**)&wkh, s_wkh);
    cudaGetSymbolAddress((void**)&wkl, s_wkl);
    cudaGetSymbolAddress((void**)&wvh, s_wvh);
    cudaGetSymbolAddress((void**)&wvl, s_wvl);
    cudaGetSymbolAddress((void**)&woh, s_woh);
    cudaGetSymbolAddress((void**)&wol, s_wol);
    cudaGetSymbolAddress((void**)&qh, s_qh);
    cudaGetSymbolAddress((void**)&ql, s_ql);
    cudaGetSymbolAddress((void**)&kh, s_kh);
    cudaGetSymbolAddress((void**)&kl, s_kl);
    cudaGetSymbolAddress((void**)&vth, s_vth);
    cudaGetSymbolAddress((void**)&vtl, s_vtl);

    cudaFuncSetAttribute(gemm_mma, cudaFuncAttributeMaxDynamicSharedMemorySize, GEMM_SMEM);
    cudaFuncSetAttribute(attn_mma, cudaFuncAttributeMaxDynamicSharedMemorySize, ATT_SMEM);

    // splits (x + weights)
    split_kernel<<<(S * DIM) / 256, 256>>>(x, xh, xl);
    split_kernel<<<(DIM * DIM) / 256, 256>>>(wq, wqh, wql);
    split_kernel<<<(DIM * DIM) / 256, 256>>>(wk, wkh, wkl);
    split_kernel<<<(DIM * DIM) / 256, 256>>>(wv, wvh, wvl);
    split_kernel<<<(DIM * DIM) / 256, 256>>>(wo, woh, wol);

    // Q/K/V projections (z-batched)
    gemm_mma<<<dim3(12, 24, 3), 256, GEMM_SMEM>>>(
        xh, xl, wqh, wql, wkh, wkl, wvh, wvl, bq, bk, bv, qp, kp, vp);

    norm_rope_kernel<<<dim3(S, 2), 256>>>(qp, kp, qh, ql, kh, kl, gq, gk, fc, fs);
    pool_mean<<<dim3(NB, 2), 256>>>(qp, kp, qwp, kwp);
    draft_scores<<<dim3(H, NB), 32>>>(qwp, kwp, bap);
    topk_thresh<<<H, 256>>>(bap, thp);
    build_lists<<<dim3(NB, H), 32>>>(bap, thp, lp, cp);
    order_pairs<<<1, NPAIR>>>(cp, op);

    vt_split<<<dim3(S / 32, DIM / 32), 256>>>(vp, vth, vtl);

    attn_mma<<<NPAIR, 256, ATT_SMEM>>>(qh, ql, kh, kl, vth, vtl, lp, cp, op, ah, al);

    // O projection
    gemm_mma<<<dim3(12, 24, 1), 256, GEMM_SMEM>>>(
        ah, al, woh, wol, woh, wol, woh, wol, bo, bo, bo, out, out, out);
}

// round 15
// speedup vs baseline: 1.1031x; 1.0367x over previous
#include <cuda_runtime.h>
#include <cuda_bf16.h>
#include <cstdint>

#define S 3072
#define DIM 1536
#define H 12
#define NB 24
#define SCALE 0.08838834764831845f   // 1/sqrt(128)
#define NEG_BIG (-1e30f)
#define NPAIR (H * NB)                // 288

// ---------------- scratch (device globals; no allocation allowed) ----------
__device__ float g_q[S * DIM];
__device__ float g_k[S * DIM];
__device__ float g_v[S * DIM];
__device__ float g_qw[NB * DIM];
__device__ float g_kw[NB * DIM];
__device__ float g_battn[H * NB * NB];
__device__ float g_thr[H];
__device__ int   g_list[H * NB * NB];
__device__ int   g_cnt[NPAIR];
__device__ int   g_order[NPAIR];

// bf16 hi/lo splits
__device__ __nv_bfloat16 s_xh[S * DIM],  s_xl[S * DIM];
__device__ __nv_bfloat16 s_ah[S * DIM],  s_al[S * DIM];
__device__ __nv_bfloat16 s_wqh[DIM * DIM], s_wql[DIM * DIM];
__device__ __nv_bfloat16 s_wkh[DIM * DIM], s_wkl[DIM * DIM];
__device__ __nv_bfloat16 s_wvh[DIM * DIM], s_wvl[DIM * DIM];
__device__ __nv_bfloat16 s_woh[DIM * DIM], s_wol[DIM * DIM];
__device__ __nv_bfloat16 s_qh[S * DIM], s_ql[S * DIM];
__device__ __nv_bfloat16 s_kh[S * DIM], s_kl[S * DIM];
__device__ __nv_bfloat16 s_vth[DIM * S], s_vtl[DIM * S];   // transposed [d][t]

// ---------------------------------------------------------------------------
__device__ __forceinline__ uint32_t smem_u32(const void* p) {
    uint32_t a;
    asm("{ .reg .u64 t; cvta.to.shared.u64 t, %1; cvt.u32.u64 %0, t; }"
        : "=r"(a) : "l"(p));
    return a;
}
__device__ __forceinline__ void cp16(uint32_t dst, const void* src) {
    asm volatile("cp.async.cg.shared.global [%0], [%1], 16;" :: "r"(dst), "l"(src));
}
#define CP_COMMIT() asm volatile("cp.async.commit_group;" ::: "memory")
#define CP_WAIT(n)  asm volatile("cp.async.wait_group %0;" :: "n"(n) : "memory")

__device__ __forceinline__ void mma_bf16(float* c, uint32_t a0, uint32_t a1,
                                         uint32_t a2, uint32_t a3,
                                         uint32_t b0, uint32_t b1) {
    asm volatile(
        "mma.sync.aligned.m16n8k16.row.col.f32.bf16.bf16.f32 "
        "{%0,%1,%2,%3}, {%4,%5,%6,%7}, {%8,%9}, {%0,%1,%2,%3};"
        : "+f"(c[0]), "+f"(c[1]), "+f"(c[2]), "+f"(c[3])
        : "r"(a0), "r"(a1), "r"(a2), "r"(a3), "r"(b0), "r"(b1));
}
__device__ __forceinline__ void ldsm_x4(uint32_t& r0, uint32_t& r1,
                                        uint32_t& r2, uint32_t& r3, uint32_t a) {
    asm volatile("ldmatrix.sync.aligned.m8n8.x4.shared.b16 {%0,%1,%2,%3}, [%4];"
                 : "=r"(r0), "=r"(r1), "=r"(r2), "=r"(r3) : "r"(a));
}
__device__ __forceinline__ uint32_t pack2(float x, float y) {
    __nv_bfloat162 t = __floats2bfloat162_rn(x, y);
    return *(uint32_t*)&t;
}

// ---------------------------------------------------------------------------
// split: fp32 -> (bf16 hi, bf16 lo), 4 elems/thread vectorized
// ---------------------------------------------------------------------------
__global__ __launch_bounds__(256) void split_kernel(
    const float* __restrict__ X, __nv_bfloat16* __restrict__ Hh,
    __nv_bfloat16* __restrict__ Hl)
{
    int i = (blockIdx.x * 256 + threadIdx.x) * 4;
    float4 v = *(const float4*)(X + i);
    uint32_t h0 = pack2(v.x, v.y), h1 = pack2(v.z, v.w);
    __nv_bfloat162 b0 = *(__nv_bfloat162*)&h0;
    __nv_bfloat162 b1 = *(__nv_bfloat162*)&h1;
    uint32_t l0 = pack2(v.x - __bfloat162float(b0.x), v.y - __bfloat162float(b0.y));
    uint32_t l1 = pack2(v.z - __bfloat162float(b1.x), v.w - __bfloat162float(b1.y));
    *(uint32_t*)(Hh + i) = h0;  *(uint32_t*)(Hh + i + 2) = h1;
    *(uint32_t*)(Hl + i) = l0;  *(uint32_t*)(Hl + i + 2) = l1;
}

// ---------------------------------------------------------------------------
__global__ __launch_bounds__(256) void vt_split(
    const float* __restrict__ V, __nv_bfloat16* __restrict__ Th,
    __nv_bfloat16* __restrict__ Tl)
{
    __shared__ float tile[32][33];
    const int t0 = blockIdx.x * 32, d0 = blockIdx.y * 32;
    const int tx = threadIdx.x & 31, ty = threadIdx.x >> 5;
#pragma unroll
    for (int i = 0; i < 4; i++)
        tile[ty + 8 * i][tx] = V[(size_t)(t0 + ty + 8 * i) * DIM + d0 + tx];
    __syncthreads();
#pragma unroll
    for (int i = 0; i < 4; i++) {
        float v = tile[tx][ty + 8 * i];
        __nv_bfloat16 h = __float2bfloat16(v);
        size_t o = (size_t)(d0 + ty + 8 * i) * S + t0 + tx;
        Th[o] = h;
        Tl[o] = __float2bfloat16(v - __bfloat162float(h));
    }
}

// ---------------------------------------------------------------------------
// mma.sync GEMM, bf16-split 3-product, 3-stage pipeline, ldmatrix frags.
// ---------------------------------------------------------------------------
#define TILEB 18432                   // 128 rows * 144B
#define STAGEB (4 * TILEB)
#define GEMM_SMEM (3 * STAGEB)

__global__ __launch_bounds__(256, 1) void gemm_mma(
    const __nv_bfloat16* __restrict__ Ah, const __nv_bfloat16* __restrict__ Al,
    const __nv_bfloat16* __restrict__ Wh0, const __nv_bfloat16* __restrict__ Wl0,
    const __nv_bfloat16* __restrict__ Wh1, const __nv_bfloat16* __restrict__ Wl1,
    const __nv_bfloat16* __restrict__ Wh2, const __nv_bfloat16* __restrict__ Wl2,
    const float* __restrict__ b0, const float* __restrict__ b1,
    const float* __restrict__ b2,
    float* __restrict__ C0, float* __restrict__ C1, float* __restrict__ C2)
{
    extern __shared__ char smem[];
    const int z = blockIdx.z;
    const __nv_bfloat16* Wh = z == 0 ? Wh0 : (z == 1 ? Wh1 : Wh2);
    const __nv_bfloat16* Wl = z == 0 ? Wl0 : (z == 1 ? Wl1 : Wl2);
    const float* bias = z == 0 ? b0 : (z == 1 ? b1 : b2);
    float* C = z == 0 ? C0 : (z == 1 ? C1 : C2);

    const int n0 = blockIdx.x * 128;
    const int m0 = blockIdx.y * 128;
    const int tid = threadIdx.x;
    const int lane = tid & 31, wid = tid >> 5;
    const int warp_m = wid & 3, warp_n = wid >> 2;
    const int g = lane >> 2, th = lane & 3;
    const int lidx = lane >> 3, lrow = lane & 7;

    const uint32_t sbase = smem_u32(smem);
    const uint32_t ga_off = (uint32_t)(warp_m * 32 + lrow + ((lane >> 3) & 1) * 8) * 144
                          + ((lane >> 4) & 1) * 16;
    const uint32_t gb_off = (uint32_t)(warp_n * 64 + lrow + (lidx >> 1) * 8) * 144
                          + (lidx & 1) * 16;

    auto load_stage = [&](int stage, int c) {
        const __nv_bfloat16* srcs[4] = {
            Ah + (size_t)m0 * DIM + c * 64,
            Al + (size_t)m0 * DIM + c * 64,
            Wh + (size_t)n0 * DIM + c * 64,
            Wl + (size_t)n0 * DIM + c * 64 };
        uint32_t stb = sbase + stage * STAGEB;
#pragma unroll
        for (int t = 0; t < 4; t++) {
#pragma unroll
            for (int u = 0; u < 4; u++) {
                int f = tid + 256 * u;
                int row = f >> 3, seg = f & 7;
                cp16(stb + t * TILEB + row * 144 + seg * 16,
                     srcs[t] + (size_t)row * DIM + seg * 8);
            }
        }
    };

    float acc[2][8][4];
#pragma unroll
    for (int i = 0; i < 2; i++)
#pragma unroll
        for (int j = 0; j < 8; j++)
#pragma unroll
            for (int r = 0; r < 4; r++) acc[i][j][r] = 0.f;

    load_stage(0, 0); CP_COMMIT();
    load_stage(1, 1); CP_COMMIT();

    for (int c = 0; c < 24; c++) {
        if (c < 23) { CP_WAIT(1); } else { CP_WAIT(0); }
        __syncthreads();

        const uint32_t stg = sbase + (c % 3) * STAGEB;
        const uint32_t sAh = stg, sAl = stg + TILEB;
        const uint32_t sWh = stg + 2 * TILEB, sWl = stg + 3 * TILEB;

#pragma unroll
        for (int ks = 0; ks < 4; ks++) {
            uint32_t ah[2][4], al[2][4];
#pragma unroll
            for (int mt = 0; mt < 2; mt++) {
                ldsm_x4(ah[mt][0], ah[mt][1], ah[mt][2], ah[mt][3],
                        sAh + ga_off + mt * 2304 + ks * 32);
                ldsm_x4(al[mt][0], al[mt][1], al[mt][2], al[mt][3],
                        sAl + ga_off + mt * 2304 + ks * 32);
            }
#pragma unroll
            for (int jp = 0; jp < 4; jp++) {
                uint32_t bh0, bh1, bh2, bh3, bl0, bl1, bl2, bl3;
                ldsm_x4(bh0, bh1, bh2, bh3, sWh + gb_off + jp * 2304 + ks * 32);
                ldsm_x4(bl0, bl1, bl2, bl3, sWl + gb_off + jp * 2304 + ks * 32);
#pragma unroll
                for (int mt = 0; mt < 2; mt++) {
                    mma_bf16(acc[mt][2 * jp], ah[mt][0], ah[mt][1], ah[mt][2], ah[mt][3], bh0, bh1);
                    mma_bf16(acc[mt][2 * jp], ah[mt][0], ah[mt][1], ah[mt][2], ah[mt][3], bl0, bl1);
                    mma_bf16(acc[mt][2 * jp], al[mt][0], al[mt][1], al[mt][2], al[mt][3], bh0, bh1);
                    mma_bf16(acc[mt][2 * jp + 1], ah[mt][0], ah[mt][1], ah[mt][2], ah[mt][3], bh2, bh3);
                    mma_bf16(acc[mt][2 * jp + 1], ah[mt][0], ah[mt][1], ah[mt][2], ah[mt][3], bl2, bl3);
                    mma_bf16(acc[mt][2 * jp + 1], al[mt][0], al[mt][1], al[mt][2], al[mt][3], bh2, bh3);
                }
            }
        }
        if (c + 2 < 24) { load_stage((c + 2) % 3, c + 2); CP_COMMIT(); }
        __syncthreads();
    }

#pragma unroll
    for (int mt = 0; mt < 2; mt++) {
        int r = m0 + warp_m * 32 + mt * 16 + g;
#pragma unroll
        for (int j = 0; j < 8; j++) {
            int col = n0 + warp_n * 64 + j * 8 + th * 2;
            float bx = bias[col], by = bias[col + 1];
            float2 o0 = { acc[mt][j][0] + bx, acc[mt][j][1] + by };
            float2 o1 = { acc[mt][j][2] + bx, acc[mt][j][3] + by };
            *(float2*)(C + (size_t)r * DIM + col) = o0;
            *(float2*)(C + (size_t)(r + 8) * DIM + col) = o1;
        }
    }
}

// ---------------------------------------------------------------------------
// RMSNorm + RoPE, fused bf16 hi/lo split output
// ---------------------------------------------------------------------------
__global__ __launch_bounds__(256) void norm_rope_kernel(
    float* __restrict__ Xq, float* __restrict__ Xk,
    __nv_bfloat16* __restrict__ Qh, __nv_bfloat16* __restrict__ Ql,
    __nv_bfloat16* __restrict__ Kh, __nv_bfloat16* __restrict__ Kl,
    const float* __restrict__ gq, const float* __restrict__ gk,
    const float* __restrict__ fc, const float* __restrict__ fs)
{
    const int s = blockIdx.x;
    float* X = blockIdx.y ? Xk : Xq;
    __nv_bfloat16* Oh = blockIdx.y ? Kh : Qh;
    __nv_bfloat16* Ol = blockIdx.y ? Kl : Ql;
    const float* g = blockIdx.y ? gk : gq;
    float* row = X + (size_t)s * 1536;
    const int tid = threadIdx.x;

    float ss = 0.f;
#pragma unroll
    for (int c = 0; c < 6; c++) {
        float v = row[tid + 256 * c];
        ss += v * v;
    }
#pragma unroll
    for (int o = 16; o >= 1; o >>= 1)
        ss += __shfl_xor_sync(0xffffffffu, ss, o);
    __shared__ float red[8];
    if ((tid & 31) == 0) red[tid >> 5] = ss;
    __syncthreads();
    float tot = 0.f;
#pragma unroll
    for (int w = 0; w < 8; w++) tot += red[w];
    float scale = rsqrtf(tot * (1.f / 1536.f) + 1e-5f);

#pragma unroll
    for (int u = 0; u < 3; u++) {
        int p = tid + 256 * u;
        int i = p & 63;
        float c = fc[s * 64 + i];
        float sn = fs[s * 64 + i];
        float x0 = row[2 * p] * scale * g[2 * p];
        float x1 = row[2 * p + 1] * scale * g[2 * p + 1];
        float y0 = x0 * c - x1 * sn;
        float y1 = x0 * sn + x1 * c;
        row[2 * p]     = y0;
        row[2 * p + 1] = y1;
        size_t o = (size_t)s * 1536 + 2 * p;
        __nv_bfloat16 h0 = __float2bfloat16(y0);
        __nv_bfloat16 h1 = __float2bfloat16(y1);
        Oh[o] = h0;     Oh[o + 1] = h1;
        Ol[o] = __float2bfloat16(y0 - __bfloat162float(h0));
        Ol[o + 1] = __float2bfloat16(y1 - __bfloat162float(h1));
    }
}

// ---------------------------------------------------------------------------
__global__ __launch_bounds__(256) void pool_mean(
    const float* __restrict__ Q, const float* __restrict__ Kx,
    float* __restrict__ qw, float* __restrict__ kw)
{
    const int nb = blockIdx.x;
    const float* X = blockIdx.y ? Kx : Q;
    float* Wo = blockIdx.y ? kw : qw;
    const int tid = threadIdx.x;
    float acc[6] = {0, 0, 0, 0, 0, 0};
    for (int t = 0; t < 128; t++) {
        const float* row = X + (size_t)(nb * 128 + t) * 1536;
#pragma unroll
        for (int c = 0; c < 6; c++) acc[c] += row[tid + 256 * c];
    }
#pragma unroll
    for (int c = 0; c < 6; c++)
        Wo[nb * 1536 + tid + 256 * c] = acc[c] * (1.f / 128.f);
}

// ---------------------------------------------------------------------------
__global__ void draft_scores(const float* __restrict__ qw,
                             const float* __restrict__ kw,
                             float* __restrict__ battn)
{
    const int h = blockIdx.x, l = blockIdx.y;
    const int m = threadIdx.x;
    float sc = NEG_BIG;
    if (m < 24) {
        int rl = l >> 2, cl = l & 3, rm = m >> 2, cm = m & 3;
        bool ok = (rm >= rl - 3) && (rm <= rl + 2) && (cm >= cl - 3) && (cm <= cl + 2);
        if (ok) {
            float sum = 0.f;
            const float* qr = qw + l * 1536 + h * 128;
            const float* kr = kw + m * 1536 + h * 128;
#pragma unroll 8
            for (int d = 0; d < 128; d++) sum += qr[d] * kr[d];
            sc = sum * SCALE;
        }
    }
    float mx = sc;
#pragma unroll
    for (int o = 16; o >= 1; o >>= 1)
        mx = fmaxf(mx, __shfl_xor_sync(0xffffffffu, mx, o));
    float e = __expf(sc - mx);
    float se = e;
#pragma unroll
    for (int o = 16; o >= 1; o >>= 1)
        se += __shfl_xor_sync(0xffffffffu, se, o);
    if (m < 24) battn[(h * 24 + l) * 24 + m] = e / se;
}

// ---------------------------------------------------------------------------
__global__ void topk_thresh(const float* __restrict__ battn, float* __restrict__ thr)
{
    const int h = blockIdx.x;
    __shared__ float buf[576];
    __shared__ float result;
    for (int e = threadIdx.x; e < 576; e += 256) buf[e] = battn[h * 576 + e];
    if (threadIdx.x == 0) result = 0.f;
    __syncthreads();
    for (int e = threadIdx.x; e < 576; e += 256) {
        float v = buf[e];
        int cg = 0, ce = 0;
        for (int x = 0; x < 576; x++) {
            cg += (buf[x] > v);
            ce += (buf[x] == v);
        }
        if (cg <= 128 && cg + ce >= 129) result = v;
    }
    __syncthreads();
    if (threadIdx.x == 0) thr[h] = result;
}

// ---------------------------------------------------------------------------
__global__ void build_lists(const float* __restrict__ battn,
                            const float* __restrict__ thr,
                            int* __restrict__ list, int* __restrict__ cnt)
{
    const int l = blockIdx.x, h = blockIdx.y;
    const int m = threadIdx.x;
    bool sel = (m < 24) && (battn[(h * 24 + l) * 24 + m] > thr[h]);
    unsigned msk = __ballot_sync(0xffffffffu, sel);
    int pos = __popc(msk & ((1u << m) - 1u));
    if (sel) list[(h * 24 + l) * 24 + pos] = m;
    if (m == 0) cnt[h * 24 + l] = __popc(msk);
}

// ---------------------------------------------------------------------------
__global__ void order_pairs(const int* __restrict__ cnt, int* __restrict__ order)
{
    __shared__ int bucket[32];
    __shared__ int base[32];
    const int tid = threadIdx.x;
    if (tid < 32) bucket[tid] = 0;
    __syncthreads();
    int nc = cnt[tid];
    atomicAdd(&bucket[nc], 1);
    __syncthreads();
    if (tid == 0) {
        int acc = 0;
        for (int v = 31; v >= 0; v--) { base[v] = acc; acc += bucket[v]; }
    }
    __syncthreads();
    int pos = atomicAdd(&base[nc], 1);
    order[pos] = tid;
}

// ---------------------------------------------------------------------------
// Block-sparse flash attention: mma.sync + ldmatrix, Q frags in registers,
// software-pipelined K/V loads (K double-buffered, V overlapped with S).
// ---------------------------------------------------------------------------
#define AT_U32 68
#define AT_TILEB (128 * AT_U32 * 4)     // 34816
#define ATT_SMEM (6 * AT_TILEB)         // 208896

__global__ __launch_bounds__(256, 1) void attn_mma(
    const __nv_bfloat16* __restrict__ Qh, const __nv_bfloat16* __restrict__ Ql,
    const __nv_bfloat16* __restrict__ Kh, const __nv_bfloat16* __restrict__ Kl,
    const __nv_bfloat16* __restrict__ Vth, const __nv_bfloat16* __restrict__ Vtl,
    const int* __restrict__ list, const int* __restrict__ cnt,
    const int* __restrict__ order,
    __nv_bfloat16* __restrict__ OAh, __nv_bfloat16* __restrict__ OAl)
{
    extern __shared__ char smem[];
    const int pair = order[blockIdx.x];
    const int h = pair / 24, l = pair % 24;
    const int tid = threadIdx.x;
    const int lane = tid & 31, wid = tid >> 5;
    const int g = lane >> 2, th = lane & 3;
    const int lidx = lane >> 3, lrow = lane & 7;
    const uint32_t sb = smem_u32(smem);
    const uint32_t T0 = sb,               T1 = sb + AT_TILEB;
    const uint32_t T2 = sb + 2 * AT_TILEB, T3 = sb + 3 * AT_TILEB;
    const uint32_t T4 = sb + 4 * AT_TILEB, T5 = sb + 5 * AT_TILEB;

    const uint32_t a_off = (uint32_t)(wid * 16 + lrow + ((lane >> 3) & 1) * 8) * 272
                         + ((lane >> 4) & 1) * 16;
    const uint32_t b_off = (uint32_t)(lrow + (lidx >> 1) * 8) * 272 + (lidx & 1) * 16;

    // ---- stage Q into T0/T1, pull fragments into registers ----
#pragma unroll
    for (int t = 0; t < 2; t++) {
        const __nv_bfloat16* src = t ? Ql : Qh;
        uint32_t dst = t ? T1 : T0;
#pragma unroll
        for (int u = 0; u < 8; u++) {
            int f = tid + 256 * u;
            int row = f >> 4, seg = f & 15;
            cp16(dst + row * 272 + seg * 16,
                 src + (size_t)(l * 128 + row) * DIM + h * 128 + seg * 8);
        }
    }
    CP_COMMIT();
    CP_WAIT(0);
    __syncthreads();

    uint32_t qfh[8][4], qfl[8][4];
#pragma unroll
    for (int ks = 0; ks < 8; ks++) {
        ldsm_x4(qfh[ks][0], qfh[ks][1], qfh[ks][2], qfh[ks][3], T0 + a_off + ks * 32);
        ldsm_x4(qfl[ks][0], qfl[ks][1], qfl[ks][2], qfl[ks][3], T1 + a_off + ks * 32);
    }
    __syncthreads();   // everyone done reading Q before T0/T1 get reused for K

    const int nc = cnt[pair];

    auto load_K = [&](int mb, uint32_t dh, uint32_t dl) {
#pragma unroll
        for (int u = 0; u < 8; u++) {
            int f = tid + 256 * u;
            int row = f >> 4, seg = f & 15;
            size_t ko = (size_t)(mb * 128 + row) * DIM + h * 128 + seg * 8;
            uint32_t so = row * 272 + seg * 16;
            cp16(dh + so, Kh + ko);
            cp16(dl + so, Kl + ko);
        }
    };
    auto load_V = [&](int mb) {
#pragma unroll
        for (int u = 0; u < 8; u++) {
            int f = tid + 256 * u;
            int row = f >> 4, seg = f & 15;
            size_t vo = (size_t)(h * 128 + row) * S + mb * 128 + seg * 8;
            uint32_t so = row * 272 + seg * 16;
            cp16(T4 + so, Vth + vo);
            cp16(T5 + so, Vtl + vo);
        }
    };

    if (nc > 0) { load_K(list[pair * 24], T2, T3); CP_COMMIT(); }

    float oacc[16][4];
#pragma unroll
    for (int j = 0; j < 16; j++)
        oacc[j][0] = oacc[j][1] = oacc[j][2] = oacc[j][3] = 0.f;
    float m0 = NEG_BIG, m1 = NEG_BIG, den0 = 0.f, den1 = 0.f;

    for (int b = 0; b < nc; b++) {
        const int mb = list[pair * 24 + b];
        __syncthreads();               // PV_{b-1} reads done before V overwrite
        load_V(mb);
        CP_COMMIT();
        CP_WAIT(1);                    // K_b landed (V_b may be in flight)
        __syncthreads();

        const uint32_t kh_b = (b & 1) ? T0 : T2;
        const uint32_t kl_b = (b & 1) ? T1 : T3;

        // ---- S = Q K^T (Q frags from registers) ----
        float sacc[16][4];
#pragma unroll
        for (int j = 0; j < 16; j++)
            sacc[j][0] = sacc[j][1] = sacc[j][2] = sacc[j][3] = 0.f;
#pragma unroll
        for (int ks = 0; ks < 8; ks++) {
#pragma unroll
            for (int jp = 0; jp < 8; jp++) {
                uint32_t kh0, kh1, kh2, kh3, kl0, kl1, kl2, kl3;
                ldsm_x4(kh0, kh1, kh2, kh3, kh_b + b_off + jp * 4352 + ks * 32);
                ldsm_x4(kl0, kl1, kl2, kl3, kl_b + b_off + jp * 4352 + ks * 32);
                mma_bf16(sacc[2 * jp], qfh[ks][0], qfh[ks][1], qfh[ks][2], qfh[ks][3], kh0, kh1);
                mma_bf16(sacc[2 * jp], qfh[ks][0], qfh[ks][1], qfh[ks][2], qfh[ks][3], kl0, kl1);
                mma_bf16(sacc[2 * jp], qfl[ks][0], qfl[ks][1], qfl[ks][2], qfl[ks][3], kh0, kh1);
                mma_bf16(sacc[2 * jp + 1], qfh[ks][0], qfh[ks][1], qfh[ks][2], qfh[ks][3], kh2, kh3);
                mma_bf16(sacc[2 * jp + 1], qfh[ks][0], qfh[ks][1], qfh[ks][2], qfh[ks][3], kl2, kl3);
                mma_bf16(sacc[2 * jp + 1], qfl[ks][0], qfl[ks][1], qfl[ks][2], qfl[ks][3], kh2, kh3);
            }
        }

        // ---- online softmax ----
        float mx0 = NEG_BIG, mx1 = NEG_BIG;
#pragma unroll
        for (int j = 0; j < 16; j++) {
            sacc[j][0] *= SCALE; sacc[j][1] *= SCALE;
            sacc[j][2] *= SCALE; sacc[j][3] *= SCALE;
            mx0 = fmaxf(mx0, fmaxf(sacc[j][0], sacc[j][1]));
            mx1 = fmaxf(mx1, fmaxf(sacc[j][2], sacc[j][3]));
        }
        mx0 = fmaxf(mx0, __shfl_xor_sync(0xffffffffu, mx0, 1));
        mx0 = fmaxf(mx0, __shfl_xor_sync(0xffffffffu, mx0, 2));
        mx1 = fmaxf(mx1, __shfl_xor_sync(0xffffffffu, mx1, 1));
        mx1 = fmaxf(mx1, __shfl_xor_sync(0xffffffffu, mx1, 2));
        float nm0 = fmaxf(m0, mx0), nm1 = fmaxf(m1, mx1);
        float f0 = __expf(m0 - nm0), f1 = __expf(m1 - nm1);
        float rs0 = 0.f, rs1 = 0.f;
#pragma unroll
        for (int j = 0; j < 16; j++) {
            sacc[j][0] = __expf(sacc[j][0] - nm0);
            sacc[j][1] = __expf(sacc[j][1] - nm0);
            sacc[j][2] = __expf(sacc[j][2] - nm1);
            sacc[j][3] = __expf(sacc[j][3] - nm1);
            rs0 += sacc[j][0] + sacc[j][1];
            rs1 += sacc[j][2] + sacc[j][3];
        }
        rs0 += __shfl_xor_sync(0xffffffffu, rs0, 1);
        rs0 += __shfl_xor_sync(0xffffffffu, rs0, 2);
        rs1 += __shfl_xor_sync(0xffffffffu, rs1, 1);
        rs1 += __shfl_xor_sync(0xffffffffu, rs1, 2);
        den0 = den0 * f0 + rs0; m0 = nm0;
        den1 = den1 * f1 + rs1; m1 = nm1;
#pragma unroll
        for (int j = 0; j < 16; j++) {
            oacc[j][0] *= f0; oacc[j][1] *= f0;
            oacc[j][2] *= f1; oacc[j][3] *= f1;
        }

        // prefetch K_{b+1} into the other K buffer (overlaps PV)
        if (b + 1 < nc) {
            load_K(list[pair * 24 + b + 1], (b & 1) ? T2 : T0, (b & 1) ? T3 : T1);
            CP_COMMIT();
            CP_WAIT(1);                // V_b landed (K_{b+1} may be in flight)
        } else {
            CP_WAIT(0);
        }
        __syncthreads();

        // ---- O += P V ----
#pragma unroll
        for (int kk = 0; kk < 8; kk++) {
            float p00 = sacc[2 * kk][0],     p01 = sacc[2 * kk][1];
            float p10 = sacc[2 * kk][2],     p11 = sacc[2 * kk][3];
            float p20 = sacc[2 * kk + 1][0], p21 = sacc[2 * kk + 1][1];
            float p30 = sacc[2 * kk + 1][2], p31 = sacc[2 * kk + 1][3];
            uint32_t ph0 = pack2(p00, p01), ph1 = pack2(p10, p11);
            uint32_t ph2 = pack2(p20, p21), ph3 = pack2(p30, p31);
            __nv_bfloat162 h0 = *(__nv_bfloat162*)&ph0;
            __nv_bfloat162 h1 = *(__nv_bfloat162*)&ph1;
            __nv_bfloat162 h2 = *(__nv_bfloat162*)&ph2;
            __nv_bfloat162 h3 = *(__nv_bfloat162*)&ph3;
            uint32_t pl0 = pack2(p00 - __bfloat162float(h0.x), p01 - __bfloat162float(h0.y));
            uint32_t pl1 = pack2(p10 - __bfloat162float(h1.x), p11 - __bfloat162float(h1.y));
            uint32_t pl2 = pack2(p20 - __bfloat162float(h2.x), p21 - __bfloat162float(h2.y));
            uint32_t pl3 = pack2(p30 - __bfloat162float(h3.x), p31 - __bfloat162float(h3.y));
#pragma unroll
            for (int jp = 0; jp < 8; jp++) {
                uint32_t vh0, vh1, vh2, vh3, vl0, vl1, vl2, vl3;
                ldsm_x4(vh0, vh1, vh2, vh3, T4 + b_off + jp * 4352 + kk * 32);
                ldsm_x4(vl0, vl1, vl2, vl3, T5 + b_off + jp * 4352 + kk * 32);
                mma_bf16(oacc[2 * jp], ph0, ph1, ph2, ph3, vh0, vh1);
                mma_bf16(oacc[2 * jp], ph0, ph1, ph2, ph3, vl0, vl1);
                mma_bf16(oacc[2 * jp], pl0, pl1, pl2, pl3, vh0, vh1);
                mma_bf16(oacc[2 * jp + 1], ph0, ph1, ph2, ph3, vh2, vh3);
                mma_bf16(oacc[2 * jp + 1], ph0, ph1, ph2, ph3, vl2, vl3);
                mma_bf16(oacc[2 * jp + 1], pl0, pl1, pl2, pl3, vh2, vh3);
            }
        }
    }

    // epilogue: normalize + bf16 hi/lo split write
    float inv0 = den0 > 0.f ? 1.f / den0 : 0.f;
    float inv1 = den1 > 0.f ? 1.f / den1 : 0.f;
    const int r0 = l * 128 + wid * 16 + g, r1 = r0 + 8;
#pragma unroll
    for (int j = 0; j < 16; j++) {
        int col = h * 128 + j * 8 + 2 * th;
        float v00 = oacc[j][0] * inv0, v01 = oacc[j][1] * inv0;
        float v10 = oacc[j][2] * inv1, v11 = oacc[j][3] * inv1;
        uint32_t h0 = pack2(v00, v01);
        uint32_t h1 = pack2(v10, v11);
        __nv_bfloat162 b0 = *(__nv_bfloat162*)&h0;
        __nv_bfloat162 b1 = *(__nv_bfloat162*)&h1;
        uint32_t l0 = pack2(v00 - __bfloat162float(b0.x), v01 - __bfloat162float(b0.y));
        uint32_t l1 = pack2(v10 - __bfloat162float(b1.x), v11 - __bfloat162float(b1.y));
        *(uint32_t*)(OAh + (size_t)r0 * DIM + col) = h0;
        *(uint32_t*)(OAl + (size_t)r0 * DIM + col) = l0;
        *(uint32_t*)(OAh + (size_t)r1 * DIM + col) = h1;
        *(uint32_t*)(OAl + (size_t)r1 * DIM + col) = l1;
    }
}

// ---------------------------------------------------------------------------
extern "C" void kernel_launch(void* const* d_in, const int* in_sizes, int n_in,
                              void* d_out, int out_size)
{
    const float* x  = (const float*)d_in[0];
    const float* wq = (const float*)d_in[1];
    const float* bq = (const float*)d_in[2];
    const float* wk = (const float*)d_in[3];
    const float* bk = (const float*)d_in[4];
    const float* wv = (const float*)d_in[5];
    const float* bv = (const float*)d_in[6];
    const float* wo = (const float*)d_in[7];
    const float* bo = (const float*)d_in[8];
    const float* gq = (const float*)d_in[9];
    const float* gk = (const float*)d_in[10];
    const float* fc = (const float*)d_in[11];
    const float* fs = (const float*)d_in[12];
    float* out = (float*)d_out;

    float *qp, *kp, *vp, *qwp, *kwp, *bap, *thp;
    int *lp, *cp, *op;
    cudaGetSymbolAddress((void**)&qp, g_q);
    cudaGetSymbolAddress((void**)&kp, g_k);
    cudaGetSymbolAddress((void**)&vp, g_v);
    cudaGetSymbolAddress((void**)&qwp, g_qw);
    cudaGetSymbolAddress((void**)&kwp, g_kw);
    cudaGetSymbolAddress((void**)&bap, g_battn);
    cudaGetSymbolAddress((void**)&thp, g_thr);
    cudaGetSymbolAddress((void**)&lp, g_list);
    cudaGetSymbolAddress((void**)&cp, g_cnt);
    cudaGetSymbolAddress((void**)&op, g_order);

    __nv_bfloat16 *xh, *xl, *ah, *al;
    __nv_bfloat16 *wqh, *wql, *wkh, *wkl, *wvh, *wvl, *woh, *wol;
    __nv_bfloat16 *qh, *ql, *kh, *kl, *vth, *vtl;
    cudaGetSymbolAddress((void**)&xh, s_xh);
    cudaGetSymbolAddress((void**)&xl, s_xl);
    cudaGetSymbolAddress((void**)&ah, s_ah);
    cudaGetSymbolAddress((void**)&al, s_al);
    cudaGetSymbolAddress((void**)&wqh, s_wqh);
    cudaGetSymbolAddress((void**)&wql, s_wql);
    cudaGetSymbolAddress((void**)&wkh, s_wkh);
    cudaGetSymbolAddress((void**)&wkl, s_wkl);
    cudaGetSymbolAddress((void**)&wvh, s_wvh);
    cudaGetSymbolAddress((void**)&wvl, s_wvl);
    cudaGetSymbolAddress((void**)&woh, s_woh);
    cudaGetSymbolAddress((void**)&wol, s_wol);
    cudaGetSymbolAddress((void**)&qh, s_qh);
    cudaGetSymbolAddress((void**)&ql, s_ql);
    cudaGetSymbolAddress((void**)&kh, s_kh);
    cudaGetSymbolAddress((void**)&kl, s_kl);
    cudaGetSymbolAddress((void**)&vth, s_vth);
    cudaGetSymbolAddress((void**)&vtl, s_vtl);

    cudaFuncSetAttribute(gemm_mma, cudaFuncAttributeMaxDynamicSharedMemorySize, GEMM_SMEM);
    cudaFuncSetAttribute(attn_mma, cudaFuncAttributeMaxDynamicSharedMemorySize, ATT_SMEM);

    // splits (x + weights), vectorized x4
    split_kernel<<<(S * DIM) / 1024, 256>>>(x, xh, xl);
    split_kernel<<<(DIM * DIM) / 1024, 256>>>(wq, wqh, wql);
    split_kernel<<<(DIM * DIM) / 1024, 256>>>(wk, wkh, wkl);
    split_kernel<<<(DIM * DIM) / 1024, 256>>>(wv, wvh, wvl);
    split_kernel<<<(DIM * DIM) / 1024, 256>>>(wo, woh, wol);

    // Q/K/V projections (z-batched)
    gemm_mma<<<dim3(12, 24, 3), 256, GEMM_SMEM>>>(
        xh, xl, wqh, wql, wkh, wkl, wvh, wvl, bq, bk, bv, qp, kp, vp);

    norm_rope_kernel<<<dim3(S, 2), 256>>>(qp, kp, qh, ql, kh, kl, gq, gk, fc, fs);
    pool_mean<<<dim3(NB, 2), 256>>>(qp, kp, qwp, kwp);
    draft_scores<<<dim3(H, NB), 32>>>(qwp, kwp, bap);
    topk_thresh<<<H, 256>>>(bap, thp);
    build_lists<<<dim3(NB, H), 32>>>(bap, thp, lp, cp);
    order_pairs<<<1, NPAIR>>>(cp, op);

    vt_split<<<dim3(S / 32, DIM / 32), 256>>>(vp, vth, vtl);

    attn_mma<<<NPAIR, 256, ATT_SMEM>>>(qh, ql, kh, kl, vth, vtl, lp, cp, op, ah, al);

    // O projection
    gemm_mma<<<dim3(12, 24, 1), 256, GEMM_SMEM>>>(
        ah, al, woh, wol, woh, wol, woh, wol, bo, bo, bo, out, out, out);
}